// round 7
// baseline (speedup 1.0000x reference)
#include <cuda_runtime.h>

// ---------------- problem constants ----------------
#define NLINES 2048
#define NEP    4096
#define NK     2048
#define NC     256
#define NTOT   6144
#define HC     128
#define WC     128
#define EB_CAP 256           // per-edge-block cap
#define SE_CAP 1024          // compacted smem edge cap (expected ~230)

// output offsets (float32, reference return-tuple order)
#define OFF_POINTS   0
#define OFF_SCORES   12288
#define OFF_DESCS    18432
#define OFF_NEWLINES 1591296
#define OFF_JIDX     1599488
#define OFF_LS       1603584

// fixed-point scales (commutative integer sums -> deterministic)
#define FX_COORD 65536.0f
#define FX_SCORE 33554432.0f

// ---------------- global scratch ----------------
__device__ int g_suppress[NK];
__device__ int g_edges[64 * EB_CAP];
__device__ int g_bcnt[64];
__device__ int g_ax[NEP];
__device__ int g_ay[NEP];
__device__ int g_as[NEP];
__device__ int g_cn[NEP];
__device__ int g_geom_done;
__device__ int g_sample_done;

// =====================================================================
// k_pre: 133 blocks x 256 thr — all CC-independent work, fully parallel
//   [0,64)    : keypoint suppression (warp scans all 4096 eps) + kp outputs
//   [64,128)  : edge build, per-block lists (overwritten every replay)
//   128       : line-score normalization + flag resets
//   [129,133) : zero one accumulator array each
// =====================================================================
__global__ void __launch_bounds__(256) k_pre(const float* __restrict__ lines,
                                             const float* __restrict__ line_sc,
                                             const float* __restrict__ kp,
                                             const float* __restrict__ ksc,
                                             float* __restrict__ out) {
    __shared__ float2 se[NEP];          // 32KB
    __shared__ int s_cnt;
    __shared__ float red[256];
    int t = threadIdx.x;
    int role = blockIdx.x;

    if (role < 128) {
        const float2* ep2 = (const float2*)lines;
        for (int i = t; i < NEP; i += 256) se[i] = ep2[i];
    }
    if (role >= 64 && role < 128 && t == 0) s_cnt = 0;
    __syncthreads();

    if (role < 64) {
        // warp handles 4 keypoints; lanes split the 4096 endpoints
        int w = t >> 5, lane = t & 31;
        int kb = (role * 8 + w) * 4;
        float kx0 = kp[2*kb],   ky0 = kp[2*kb+1];
        float kx1 = kp[2*kb+2], ky1 = kp[2*kb+3];
        float kx2 = kp[2*kb+4], ky2 = kp[2*kb+5];
        float kx3 = kp[2*kb+6], ky3 = kp[2*kb+7];
        bool f0=false, f1=false, f2=false, f3=false;
        for (int j = lane; j < NEP; j += 32) {
            float2 e = se[j];
            float dx, dy;
            dx = kx0-e.x; dy = ky0-e.y; f0 |= (dx*dx+dy*dy < 16.0f);
            dx = kx1-e.x; dy = ky1-e.y; f1 |= (dx*dx+dy*dy < 16.0f);
            dx = kx2-e.x; dy = ky2-e.y; f2 |= (dx*dx+dy*dy < 16.0f);
            dx = kx3-e.x; dy = ky3-e.y; f3 |= (dx*dx+dy*dy < 16.0f);
        }
        int a0 = __any_sync(0xffffffffu, f0);
        int a1 = __any_sync(0xffffffffu, f1);
        int a2 = __any_sync(0xffffffffu, f2);
        int a3 = __any_sync(0xffffffffu, f3);
        if (lane < 4) {
            int k = kb + lane;
            int sup = (lane == 0) ? a0 : (lane == 1) ? a1 : (lane == 2) ? a2 : a3;
            g_suppress[k] = sup;
            out[OFF_POINTS + 2*(NEP + k)]     = sup ? 0.f : kp[2*k];
            out[OFF_POINTS + 2*(NEP + k) + 1] = sup ? 0.f : kp[2*k + 1];
            out[OFF_SCORES + NEP + k]         = sup ? 0.f : ksc[k];
        }
    } else if (role < 128) {
        int b = role - 64;
        int ib = b * 64 + (t >> 4) * 4;
        int jc = (t & 15) * 256;
        float2 p0 = se[ib], p1 = se[ib+1], p2 = se[ib+2], p3 = se[ib+3];
        for (int j = jc; j < jc + 256; ++j) {
            float2 e = se[j];
            float dx, dy;
            dx = p0.x-e.x; dy = p0.y-e.y;
            if (j > ib   && dx*dx+dy*dy <= 9.0f) { int x = atomicAdd(&s_cnt,1); if (x < EB_CAP) g_edges[b*EB_CAP+x] = (ib    <<16)|j; }
            dx = p1.x-e.x; dy = p1.y-e.y;
            if (j > ib+1 && dx*dx+dy*dy <= 9.0f) { int x = atomicAdd(&s_cnt,1); if (x < EB_CAP) g_edges[b*EB_CAP+x] = ((ib+1)<<16)|j; }
            dx = p2.x-e.x; dy = p2.y-e.y;
            if (j > ib+2 && dx*dx+dy*dy <= 9.0f) { int x = atomicAdd(&s_cnt,1); if (x < EB_CAP) g_edges[b*EB_CAP+x] = ((ib+2)<<16)|j; }
            dx = p3.x-e.x; dy = p3.y-e.y;
            if (j > ib+3 && dx*dx+dy*dy <= 9.0f) { int x = atomicAdd(&s_cnt,1); if (x < EB_CAP) g_edges[b*EB_CAP+x] = ((ib+3)<<16)|j; }
        }
        __syncthreads();
        if (t == 0) g_bcnt[b] = s_cnt < EB_CAP ? s_cnt : EB_CAP;
    } else if (role == 128) {
        if (t == 0) { g_geom_done = 0; g_sample_done = 0; }   // stream-ordered before k_all spins
        float v = -1e30f;
        for (int k = t; k < NLINES; k += 256) v = fmaxf(v, line_sc[k]);
        red[t] = v;
        __syncthreads();
        for (int s = 128; s > 0; s >>= 1) {
            if (t < s) red[t] = fmaxf(red[t], red[t + s]);
            __syncthreads();
        }
        float denom = 1e-8f + red[0];
        for (int k = t; k < NLINES; k += 256) out[OFF_LS + k] = line_sc[k] / denom;
    } else {
        int a = role - 129;
        int* arr = (a == 0) ? g_ax : (a == 1) ? g_ay : (a == 2) ? g_as : g_cn;
        for (int i = t; i < NEP; i += 256) arr[i] = 0;
    }
}

// =====================================================================
// k_all: 641 blocks x 512 thr, 64KB dyn smem
//   0         : geom (CC + rank + segment means + small outputs)
//   [1,257)   : masked keypoint-descriptor float4 copy (no spin)
//   [257,513) : samplers: stage plane -> spin geom_done -> sample
//   [513,641) : normalizers: spin sample_done==256 -> L2-normalize
// =====================================================================
__global__ void __launch_bounds__(512) k_all(const float* __restrict__ lines,
                                             const float* __restrict__ allD,
                                             const float* __restrict__ desc,
                                             float* __restrict__ out) {
    extern __shared__ int dsm[];
    int t = threadIdx.x;
    int role = blockIdx.x;

    if (role == 0) {
        // ---------------- geom ----------------
        int* lab  = dsm;            // 4096
        int* rnk  = dsm + 4096;     // 4096
        int* imap = dsm + 8192;     // 4096
        int* sE   = dsm + 12288;    // SE_CAP
        int* scn  = dsm + 13312;    // 512
        int* soff = dsm + 13824;    // 65
        int* misc = dsm + 13890;    // 2

        if (t == 0) {
            int acc = 0;
            for (int b = 0; b < 64; ++b) { soff[b] = acc; acc += g_bcnt[b]; }
            soff[64] = acc;
        }
        for (int i = t; i < NEP; i += 512) lab[i] = i;
        __syncthreads();
        int E = soff[64]; if (E > SE_CAP) E = SE_CAP;
        for (int s = t; s < 64 * EB_CAP; s += 512) {
            int b = s >> 8, e = s & (EB_CAP - 1);
            if (e < g_bcnt[b]) { int d = soff[b] + e; if (d < SE_CAP) sE[d] = g_edges[s]; }
        }
        __syncthreads();

        // CC min-label fixpoint (schedule-invariant)
        for (int it = 0; it < 64; ++it) {
            if (t == 0) misc[1] = 0;
            __syncthreads();
            for (int e = t; e < E; e += 512) {
                int pr = sE[e];
                int i = pr >> 16, j = pr & 0xffff;
                int a = lab[i], b = lab[j];
                if (a < b)      { int old = atomicMin(&lab[j], a); if (old > a) misc[1] = 1; }
                else if (b < a) { int old = atomicMin(&lab[i], b); if (old > b) misc[1] = 1; }
            }
            __syncthreads();
            for (int i = t; i < NEP; i += 512) {
                int l = lab[i], l2 = lab[l];
                if (l2 < l) { lab[i] = l2; misc[1] = 1; }
            }
            __syncthreads();
            int ch = misc[1];
            __syncthreads();
            if (!ch) break;
        }

        // dense rank of roots (8 flags/thread, 512-scan)
        {
            int base = t * 8;
            int p8[8], pre[8], lsum = 0;
            #pragma unroll
            for (int k = 0; k < 8; ++k) {
                p8[k] = (lab[base + k] == base + k) ? 1 : 0;
                pre[k] = lsum;
                lsum += p8[k];
            }
            scn[t] = lsum;
            __syncthreads();
            for (int off = 1; off < 512; off <<= 1) {
                int add = 0;
                if (t >= off) add = scn[t - off];
                __syncthreads();
                scn[t] += add;
                __syncthreads();
            }
            int excl = scn[t] - lsum;
            #pragma unroll
            for (int k = 0; k < 8; ++k) rnk[base + k] = excl + pre[k];
        }
        __syncthreads();

        for (int s = t; s < NEP; s += 512) imap[s] = -1;
        __syncthreads();
        for (int i = t; i < NEP; i += 512)
            if (lab[i] == i) imap[rnk[i]] = i;
        __syncthreads();

        // fixed-point segment sums into global scratch (zeroed in k_pre)
        const float2* ep2 = (const float2*)lines;
        for (int i = t; i < NEP; i += 512) {
            float2 e = ep2[i];
            float sc = out[OFF_LS + (i >> 1)];
            int r = lab[i];
            atomicAdd(&g_ax[r], __float2int_rn(e.x * FX_COORD));
            atomicAdd(&g_ay[r], __float2int_rn(e.y * FX_COORD));
            atomicAdd(&g_as[r], __float2int_rn(sc * FX_SCORE));
            atomicAdd(&g_cn[r], 1);
        }
        __syncthreads();

        // junction points/scores (L2-bypassing reads of the accumulators)
        for (int s = t; s < NEP; s += 512) {
            int r = imap[s];
            float jx = 0.f, jy = 0.f, js = 0.f;
            if (r >= 0) {
                float ic = 1.0f / (float)__ldcg(&g_cn[r]);
                jx = (float)__ldcg(&g_ax[r]) * (1.0f / FX_COORD) * ic;
                jy = (float)__ldcg(&g_ay[r]) * (1.0f / FX_COORD) * ic;
                js = (float)__ldcg(&g_as[r]) * (1.0f / FX_SCORE) * ic;
            }
            out[OFF_POINTS + 2*s]     = jx;
            out[OFF_POINTS + 2*s + 1] = jy;
            out[OFF_SCORES + s]       = js;
        }
        for (int e = t; e < NEP; e += 512) {
            int r = lab[e];
            float ic = 1.0f / (float)__ldcg(&g_cn[r]);
            out[OFF_NEWLINES + 2*e]     = (float)__ldcg(&g_ax[r]) * (1.0f / FX_COORD) * ic;
            out[OFF_NEWLINES + 2*e + 1] = (float)__ldcg(&g_ay[r]) * (1.0f / FX_COORD) * ic;
            out[OFF_JIDX + e]           = (float)rnk[r];
        }
        __threadfence();
        __syncthreads();
        if (t == 0) atomicExch(&g_geom_done, 1);
    } else if (role < 257) {
        // ---------------- keypoint-descriptor copy ----------------
        int idx = (role - 1) * 512 + t;          // 131072 float4s
        int c  = idx >> 9;
        int kq = idx & 511;
        const float4* d4 = (const float4*)desc;
        float4 v = d4[c * 512 + kq];
        int k4 = kq * 4;
        if (g_suppress[k4])     v.x = 0.f;
        if (g_suppress[k4 + 1]) v.y = 0.f;
        if (g_suppress[k4 + 2]) v.z = 0.f;
        if (g_suppress[k4 + 3]) v.w = 0.f;
        float4* o4 = (float4*)(out + OFF_DESCS + c * NTOT + NEP);
        o4[kq] = v;
    } else if (role < 513) {
        // ---------------- samplers: stage plane, THEN wait for geom ----------------
        float* spl = (float*)dsm;
        int ch = role - 257;
        const float4* src = (const float4*)(allD + (size_t)ch * (HC * WC));
        float4* dst = (float4*)spl;
        #pragma unroll
        for (int i = 0; i < 8; ++i) dst[i * 512 + t] = src[i * 512 + t];
        __syncthreads();

        if (t == 0) {
            while (atomicAdd(&g_geom_done, 0) == 0) __nanosleep(128);
        }
        __syncthreads();
        __threadfence();

        float* orow = out + OFF_DESCS + (size_t)ch * NTOT;
        const float2* pts = (const float2*)(out + OFF_POINTS);
        #pragma unroll
        for (int it = 0; it < 8; ++it) {
            int p = it * 512 + t;
            float2 pt = pts[p];
            float fx = ((pt.x - 3.5f) / 1019.5f) * 127.0f;    // folded (g+1)*0.5*(w-1)
            float fy = ((pt.y - 3.5f) / 1019.5f) * 127.0f;
            float x0 = fminf(fmaxf(floorf(fx), 0.f), 127.f);
            float y0 = fminf(fmaxf(floorf(fy), 0.f), 127.f);
            float x1 = fminf(fmaxf(x0 + 1.0f, 0.f), 127.f);
            float y1 = fminf(fmaxf(y0 + 1.0f, 0.f), 127.f);
            float wx = fx - x0;
            float wy = fy - y0;
            int a00 = (int)y0 * WC + (int)x0;
            int a01 = (int)y0 * WC + (int)x1;
            int a10 = (int)y1 * WC + (int)x0;
            int a11 = (int)y1 * WC + (int)x1;
            float v = spl[a00] * (1.f - wx) * (1.f - wy)
                    + spl[a01] * wx * (1.f - wy)
                    + spl[a10] * (1.f - wx) * wy
                    + spl[a11] * wx * wy;
            orow[p] = v;
        }
        __threadfence();
        __syncthreads();
        if (t == 0) atomicAdd(&g_sample_done, 1);
    } else {
        // ---------------- normalizers ----------------
        if (t == 0) {
            while (atomicAdd(&g_sample_done, 0) < 256) __nanosleep(256);
        }
        __syncthreads();
        __threadfence();

        int w = t >> 5, lane = t & 31;        // 16 warps, 16 channels each
        int p = (role - 513) * 32 + lane;
        float* ob = out + OFF_DESCS + (size_t)w * 16 * NTOT + p;
        float v[16];
        float ssq = 0.f;
        #pragma unroll
        for (int ci = 0; ci < 16; ++ci) {
            float vv = ob[ci * NTOT];
            v[ci] = vv;
            ssq += vv * vv;
        }
        float* sred = (float*)dsm;            // [16][32]
        sred[w * 32 + lane] = ssq;
        __syncthreads();
        float tot = 0.f;
        #pragma unroll
        for (int i = 0; i < 16; ++i) tot += sred[i * 32 + lane];
        float inv = 1.0f / fmaxf(sqrtf(tot), 1e-12f);
        #pragma unroll
        for (int ci = 0; ci < 16; ++ci)
            ob[ci * NTOT] = v[ci] * inv;
    }
}

// ---------------- launch ----------------
extern "C" void kernel_launch(void* const* d_in, const int* in_sizes, int n_in,
                              void* d_out, int out_size) {
    const float* lines     = (const float*)d_in[0];
    const float* line_sc   = (const float*)d_in[1];
    const float* keypoints = (const float*)d_in[2];
    const float* kp_sc     = (const float*)d_in[3];
    const float* desc      = (const float*)d_in[4];
    const float* allD      = (const float*)d_in[5];
    float* out = (float*)d_out;

    static const int ALL_SMEM = HC * WC * 4;     // 64KB (covers geom's 55.6KB too)
    cudaFuncSetAttribute(k_all, cudaFuncAttributeMaxDynamicSharedMemorySize, ALL_SMEM);

    k_pre<<<133, 256>>>(lines, line_sc, keypoints, kp_sc, out);
    k_all<<<641, 512, ALL_SMEM>>>(lines, allD, desc, out);
}

// round 8
// speedup vs baseline: 1.1773x; 1.1773x over previous
#include <cuda_runtime.h>

// ---------------- problem constants ----------------
#define NLINES 2048
#define NEP    4096
#define NK     2048
#define NC     256
#define NTOT   6144
#define HC     128
#define WC     128
#define EB_CAP 256
#define SE_CAP 1024

// output offsets (float32, reference return-tuple order)
#define OFF_POINTS   0
#define OFF_SCORES   12288
#define OFF_DESCS    18432
#define OFF_NEWLINES 1591296
#define OFF_JIDX     1599488
#define OFF_LS       1603584

// fixed-point scales (commutative integer sums -> deterministic)
#define FX_COORD 65536.0f
#define FX_SCORE 33554432.0f

// ---------------- global scratch ----------------
__device__ int g_suppress[NK];
__device__ int g_edges[64 * EB_CAP];
__device__ int g_bcnt[64];
__device__ int g_sample_done;

// =====================================================================
// k_pre: 129 blocks x 256 thr — all CC-independent work, fully parallel
//   [0,64)   : keypoint suppression (warp scans all 4096 eps) + kp outputs
//   [64,128) : edge build, per-block lists (overwritten every replay)
//   128      : line-score normalization
// =====================================================================
__global__ void __launch_bounds__(256) k_pre(const float* __restrict__ lines,
                                             const float* __restrict__ line_sc,
                                             const float* __restrict__ kp,
                                             const float* __restrict__ ksc,
                                             float* __restrict__ out) {
    __shared__ float2 se[NEP];
    __shared__ int s_cnt;
    __shared__ float red[256];
    int t = threadIdx.x;
    int role = blockIdx.x;

    if (role < 128) {
        const float2* ep2 = (const float2*)lines;
        for (int i = t; i < NEP; i += 256) se[i] = ep2[i];
    }
    if (role >= 64 && role < 128 && t == 0) s_cnt = 0;
    __syncthreads();

    if (role < 64) {
        int w = t >> 5, lane = t & 31;
        int kb = (role * 8 + w) * 4;
        float kx0 = kp[2*kb],   ky0 = kp[2*kb+1];
        float kx1 = kp[2*kb+2], ky1 = kp[2*kb+3];
        float kx2 = kp[2*kb+4], ky2 = kp[2*kb+5];
        float kx3 = kp[2*kb+6], ky3 = kp[2*kb+7];
        bool f0=false, f1=false, f2=false, f3=false;
        for (int j = lane; j < NEP; j += 32) {
            float2 e = se[j];
            float dx, dy;
            dx = kx0-e.x; dy = ky0-e.y; f0 |= (dx*dx+dy*dy < 16.0f);
            dx = kx1-e.x; dy = ky1-e.y; f1 |= (dx*dx+dy*dy < 16.0f);
            dx = kx2-e.x; dy = ky2-e.y; f2 |= (dx*dx+dy*dy < 16.0f);
            dx = kx3-e.x; dy = ky3-e.y; f3 |= (dx*dx+dy*dy < 16.0f);
        }
        int a0 = __any_sync(0xffffffffu, f0);
        int a1 = __any_sync(0xffffffffu, f1);
        int a2 = __any_sync(0xffffffffu, f2);
        int a3 = __any_sync(0xffffffffu, f3);
        if (lane < 4) {
            int k = kb + lane;
            int sup = (lane == 0) ? a0 : (lane == 1) ? a1 : (lane == 2) ? a2 : a3;
            g_suppress[k] = sup;
            out[OFF_POINTS + 2*(NEP + k)]     = sup ? 0.f : kp[2*k];
            out[OFF_POINTS + 2*(NEP + k) + 1] = sup ? 0.f : kp[2*k + 1];
            out[OFF_SCORES + NEP + k]         = sup ? 0.f : ksc[k];
        }
    } else if (role < 128) {
        int b = role - 64;
        int ib = b * 64 + (t >> 4) * 4;
        int jc = (t & 15) * 256;
        float2 p0 = se[ib], p1 = se[ib+1], p2 = se[ib+2], p3 = se[ib+3];
        for (int j = jc; j < jc + 256; ++j) {
            float2 e = se[j];
            float dx, dy;
            dx = p0.x-e.x; dy = p0.y-e.y;
            if (j > ib   && dx*dx+dy*dy <= 9.0f) { int x = atomicAdd(&s_cnt,1); if (x < EB_CAP) g_edges[b*EB_CAP+x] = (ib    <<16)|j; }
            dx = p1.x-e.x; dy = p1.y-e.y;
            if (j > ib+1 && dx*dx+dy*dy <= 9.0f) { int x = atomicAdd(&s_cnt,1); if (x < EB_CAP) g_edges[b*EB_CAP+x] = ((ib+1)<<16)|j; }
            dx = p2.x-e.x; dy = p2.y-e.y;
            if (j > ib+2 && dx*dx+dy*dy <= 9.0f) { int x = atomicAdd(&s_cnt,1); if (x < EB_CAP) g_edges[b*EB_CAP+x] = ((ib+2)<<16)|j; }
            dx = p3.x-e.x; dy = p3.y-e.y;
            if (j > ib+3 && dx*dx+dy*dy <= 9.0f) { int x = atomicAdd(&s_cnt,1); if (x < EB_CAP) g_edges[b*EB_CAP+x] = ((ib+3)<<16)|j; }
        }
        __syncthreads();
        if (t == 0) g_bcnt[b] = s_cnt < EB_CAP ? s_cnt : EB_CAP;
    } else {
        float v = -1e30f;
        for (int k = t; k < NLINES; k += 256) v = fmaxf(v, line_sc[k]);
        red[t] = v;
        __syncthreads();
        for (int s = 128; s > 0; s >>= 1) {
            if (t < s) red[t] = fmaxf(red[t], red[t + s]);
            __syncthreads();
        }
        float denom = 1e-8f + red[0];
        for (int k = t; k < NLINES; k += 256) out[OFF_LS + k] = line_sc[k] / denom;
    }
}

// =====================================================================
// k_geom: ONE block x 1024 thr, slim — edge compact, CC, rank,
// smem fixed-point segment means, small outputs. ~123KB dyn smem.
// =====================================================================
__global__ void __launch_bounds__(1024) k_geom(const float* __restrict__ lines,
                                               float* __restrict__ out) {
    extern __shared__ int dsm[];
    int* lab  = dsm;             // 4096
    int* rnk  = dsm + 4096;      // 4096
    int* imap = dsm + 8192;      // 4096
    int* ax   = dsm + 12288;     // 4096
    int* ay   = dsm + 16384;     // 4096
    int* as_  = dsm + 20480;     // 4096
    int* cn   = dsm + 24576;     // 4096
    int* sE   = dsm + 28672;     // SE_CAP
    int* scn  = dsm + 29696;     // 1024
    int* soff = dsm + 30720;     // 65
    int* misc = dsm + 30786;     // 2

    int t = threadIdx.x;
    if (t == 0) g_sample_done = 0;      // reset for k_main (stream-ordered)

    if (t == 0) {
        int acc = 0;
        for (int b = 0; b < 64; ++b) { soff[b] = acc; acc += g_bcnt[b]; }
        soff[64] = acc;
    }
    for (int i = t; i < NEP; i += 1024) {
        lab[i] = i;
        ax[i] = 0; ay[i] = 0; as_[i] = 0; cn[i] = 0; imap[i] = -1;
    }
    __syncthreads();
    int E = soff[64]; if (E > SE_CAP) E = SE_CAP;
    for (int s = t; s < 64 * EB_CAP; s += 1024) {
        int b = s >> 8, e = s & (EB_CAP - 1);
        if (e < g_bcnt[b]) { int d = soff[b] + e; if (d < SE_CAP) sE[d] = g_edges[s]; }
    }
    __syncthreads();

    // CC min-label fixpoint (schedule-invariant unique result)
    for (int it = 0; it < 64; ++it) {
        if (t == 0) misc[1] = 0;
        __syncthreads();
        for (int e = t; e < E; e += 1024) {
            int pr = sE[e];
            int i = pr >> 16, j = pr & 0xffff;
            int a = lab[i], b = lab[j];
            if (a < b)      { int old = atomicMin(&lab[j], a); if (old > a) misc[1] = 1; }
            else if (b < a) { int old = atomicMin(&lab[i], b); if (old > b) misc[1] = 1; }
        }
        __syncthreads();
        for (int i = t; i < NEP; i += 1024) {
            int l = lab[i], l2 = lab[l];
            if (l2 < l) { lab[i] = l2; misc[1] = 1; }
        }
        __syncthreads();
        int ch = misc[1];
        __syncthreads();
        if (!ch) break;
    }

    // dense rank of roots
    {
        int base = t * 4;
        int p4[4], pre[4], lsum = 0;
        #pragma unroll
        for (int k = 0; k < 4; ++k) {
            p4[k] = (lab[base + k] == base + k) ? 1 : 0;
            pre[k] = lsum;
            lsum += p4[k];
        }
        scn[t] = lsum;
        __syncthreads();
        for (int off = 1; off < 1024; off <<= 1) {
            int add = 0;
            if (t >= off) add = scn[t - off];
            __syncthreads();
            scn[t] += add;
            __syncthreads();
        }
        int excl = scn[t] - lsum;
        #pragma unroll
        for (int k = 0; k < 4; ++k) rnk[base + k] = excl + pre[k];
    }
    __syncthreads();
    for (int i = t; i < NEP; i += 1024)
        if (lab[i] == i) imap[rnk[i]] = i;
    __syncthreads();

    // fixed-point segment sums (smem atomics, commutative)
    const float2* ep2 = (const float2*)lines;
    for (int i = t; i < NEP; i += 1024) {
        float2 e = ep2[i];
        float sc = out[OFF_LS + (i >> 1)];
        int r = lab[i];
        atomicAdd(&ax[r],  __float2int_rn(e.x * FX_COORD));
        atomicAdd(&ay[r],  __float2int_rn(e.y * FX_COORD));
        atomicAdd(&as_[r], __float2int_rn(sc * FX_SCORE));
        atomicAdd(&cn[r], 1);
    }
    __syncthreads();

    for (int s = t; s < NEP; s += 1024) {
        int r = imap[s];
        float jx = 0.f, jy = 0.f, js = 0.f;
        if (r >= 0) {
            float ic = 1.0f / (float)cn[r];
            jx = (float)ax[r]  * (1.0f / FX_COORD) * ic;
            jy = (float)ay[r]  * (1.0f / FX_COORD) * ic;
            js = (float)as_[r] * (1.0f / FX_SCORE) * ic;
        }
        out[OFF_POINTS + 2*s]     = jx;
        out[OFF_POINTS + 2*s + 1] = jy;
        out[OFF_SCORES + s]       = js;
    }
    for (int e = t; e < NEP; e += 1024) {
        int r = lab[e];
        float ic = 1.0f / (float)cn[r];
        out[OFF_NEWLINES + 2*e]     = (float)ax[r] * (1.0f / FX_COORD) * ic;
        out[OFF_NEWLINES + 2*e + 1] = (float)ay[r] * (1.0f / FX_COORD) * ic;
        out[OFF_JIDX + e]           = (float)rnk[r];
    }
}

// =====================================================================
// k_main: 896 blocks x 256 thr, 64KB dyn smem  (R6-proven: 19.2us)
//   [0,256)   : channel-plane staged sampling (unnormalized) -> done++
//   [256,768) : float4 keypoint-descriptor copy (masked)
//   [768,896) : normalize (tail spin until done==256; consumers only)
// =====================================================================
__global__ void __launch_bounds__(256) k_main(const float* __restrict__ allD,
                                              const float* __restrict__ desc,
                                              float* __restrict__ out) {
    extern __shared__ float spl[];
    int t = threadIdx.x;
    int role = blockIdx.x;

    if (role < 256) {
        const float4* src = (const float4*)(allD + (size_t)role * (HC * WC));
        float4* dst = (float4*)spl;
        #pragma unroll
        for (int i = 0; i < 16; ++i) dst[i * 256 + t] = src[i * 256 + t];
        __syncthreads();

        float* orow = out + OFF_DESCS + (size_t)role * NTOT;
        const float2* pts = (const float2*)(out + OFF_POINTS);
        #pragma unroll
        for (int it = 0; it < 16; ++it) {
            int p = it * 256 + t;
            float2 pt = pts[p];
            float fx = ((pt.x - 3.5f) / 1019.5f) * 127.0f;   // folded (g+1)*0.5*(w-1)
            float fy = ((pt.y - 3.5f) / 1019.5f) * 127.0f;
            float x0 = fminf(fmaxf(floorf(fx), 0.f), 127.f);
            float y0 = fminf(fmaxf(floorf(fy), 0.f), 127.f);
            float x1 = fminf(fmaxf(x0 + 1.0f, 0.f), 127.f);
            float y1 = fminf(fmaxf(y0 + 1.0f, 0.f), 127.f);
            float wx = fx - x0;
            float wy = fy - y0;
            int a00 = (int)y0 * WC + (int)x0;
            int a01 = (int)y0 * WC + (int)x1;
            int a10 = (int)y1 * WC + (int)x0;
            int a11 = (int)y1 * WC + (int)x1;
            float v = spl[a00] * (1.f - wx) * (1.f - wy)
                    + spl[a01] * wx * (1.f - wy)
                    + spl[a10] * (1.f - wx) * wy
                    + spl[a11] * wx * wy;
            orow[p] = v;
        }
        __threadfence();
        __syncthreads();
        if (t == 0) atomicAdd(&g_sample_done, 1);
    } else if (role < 768) {
        int idx = (role - 256) * 256 + t;
        int c  = idx >> 9;
        int kq = idx & 511;
        const float4* d4 = (const float4*)desc;
        float4 v = d4[c * 512 + kq];
        int k4 = kq * 4;
        if (g_suppress[k4])     v.x = 0.f;
        if (g_suppress[k4 + 1]) v.y = 0.f;
        if (g_suppress[k4 + 2]) v.z = 0.f;
        if (g_suppress[k4 + 3]) v.w = 0.f;
        float4* o4 = (float4*)(out + OFF_DESCS + c * NTOT + NEP);
        o4[kq] = v;
    } else {
        if (t == 0) {
            while (atomicAdd(&g_sample_done, 0) < 256) __nanosleep(256);
        }
        __syncthreads();
        __threadfence();

        int w = t >> 5, lane = t & 31;
        int p = (role - 768) * 32 + lane;
        float* ob = out + OFF_DESCS + (size_t)w * 32 * NTOT + p;
        float v[32];
        float ssq = 0.f;
        #pragma unroll
        for (int ci = 0; ci < 32; ++ci) {
            float vv = ob[ci * NTOT];
            v[ci] = vv;
            ssq += vv * vv;
        }
        __shared__ float sred[8][32];
        sred[w][lane] = ssq;
        __syncthreads();
        float tot = sred[0][lane] + sred[1][lane] + sred[2][lane] + sred[3][lane]
                  + sred[4][lane] + sred[5][lane] + sred[6][lane] + sred[7][lane];
        float inv = 1.0f / fmaxf(sqrtf(tot), 1e-12f);
        #pragma unroll
        for (int ci = 0; ci < 32; ++ci)
            ob[ci * NTOT] = v[ci] * inv;
    }
}

// ---------------- launch ----------------
extern "C" void kernel_launch(void* const* d_in, const int* in_sizes, int n_in,
                              void* d_out, int out_size) {
    const float* lines     = (const float*)d_in[0];
    const float* line_sc   = (const float*)d_in[1];
    const float* keypoints = (const float*)d_in[2];
    const float* kp_sc     = (const float*)d_in[3];
    const float* desc      = (const float*)d_in[4];
    const float* allD      = (const float*)d_in[5];
    float* out = (float*)d_out;

    static const int GEOM_SMEM  = (30786 + 4) * 4;   // ~123 KB
    static const int PLANE_SMEM = HC * WC * 4;       // 64 KB
    cudaFuncSetAttribute(k_geom, cudaFuncAttributeMaxDynamicSharedMemorySize, GEOM_SMEM);
    cudaFuncSetAttribute(k_main, cudaFuncAttributeMaxDynamicSharedMemorySize, PLANE_SMEM);

    k_pre<<<129, 256>>>(lines, line_sc, keypoints, kp_sc, out);
    k_geom<<<1, 1024, GEOM_SMEM>>>(lines, out);
    k_main<<<896, 256, PLANE_SMEM>>>(allD, desc, out);
}

// round 9
// speedup vs baseline: 1.3342x; 1.1333x over previous
#include <cuda_runtime.h>

// ---------------- problem constants ----------------
#define NLINES 2048
#define NEP    4096
#define NK     2048
#define NC     256
#define NTOT   6144
#define HC     128
#define WC     128
#define EB_CAP 64            // per-edge-block cap (256 blocks, expected ~1 each)
#define SE_CAP 1024

// output offsets (float32, reference return-tuple order)
#define OFF_POINTS   0
#define OFF_SCORES   12288
#define OFF_DESCS    18432
#define OFF_NEWLINES 1591296
#define OFF_JIDX     1599488
#define OFF_LS       1603584

// fixed-point scales (commutative integer sums -> deterministic)
#define FX_COORD 65536.0f
#define FX_SCORE 33554432.0f

// ---------------- global scratch ----------------
__device__ int g_sup4[4 * NK];        // per-ep-quarter suppression flags (each written once)
__device__ int g_suppress[NK];        // merged (written by k_geom, read by k_main)
__device__ int g_edges[256 * EB_CAP];
__device__ int g_bcnt[256];
__device__ int g_sample_done;

// =====================================================================
// k_pre: 513 blocks x 256 thr — quadratic passes split on BOTH axes
//   [0,256)   : suppression; block = (kp-group kg of 32) x (ep-quarter q)
//   [256,512) : edges; block = (i-range ig of 64) x (j-quarter jq)
//   512       : line-score normalization
// =====================================================================
__global__ void __launch_bounds__(256) k_pre(const float* __restrict__ lines,
                                             const float* __restrict__ line_sc,
                                             const float* __restrict__ kp,
                                             float* __restrict__ out) {
    __shared__ float2 sj[1024];     // staged endpoint quarter (8KB)
    __shared__ float2 si[64];       // staged i-range (edge blocks)
    __shared__ int s_cnt;
    __shared__ float red[256];
    int t = threadIdx.x;
    int role = blockIdx.x;
    const float2* ep2 = (const float2*)lines;

    if (role < 256) {
        // ---- suppression ----
        int q  = role & 3;          // endpoint quarter
        int kg = role >> 2;         // keypoint group (32 kp)
        for (int i = t; i < 1024; i += 256) sj[i] = ep2[q * 1024 + i];
        __syncthreads();

        int w = t >> 5, lane = t & 31;
        int kb = kg * 32 + w * 4;   // 4 keypoints per warp
        float kx0 = kp[2*kb],   ky0 = kp[2*kb+1];
        float kx1 = kp[2*kb+2], ky1 = kp[2*kb+3];
        float kx2 = kp[2*kb+4], ky2 = kp[2*kb+5];
        float kx3 = kp[2*kb+6], ky3 = kp[2*kb+7];
        bool f0=false, f1=false, f2=false, f3=false;
        #pragma unroll 4
        for (int j = lane; j < 1024; j += 32) {
            float2 e = sj[j];
            float dx, dy;
            dx = kx0-e.x; dy = ky0-e.y; f0 |= (dx*dx+dy*dy < 16.0f);
            dx = kx1-e.x; dy = ky1-e.y; f1 |= (dx*dx+dy*dy < 16.0f);
            dx = kx2-e.x; dy = ky2-e.y; f2 |= (dx*dx+dy*dy < 16.0f);
            dx = kx3-e.x; dy = ky3-e.y; f3 |= (dx*dx+dy*dy < 16.0f);
        }
        int a0 = __any_sync(0xffffffffu, f0);
        int a1 = __any_sync(0xffffffffu, f1);
        int a2 = __any_sync(0xffffffffu, f2);
        int a3 = __any_sync(0xffffffffu, f3);
        if (lane < 4) {
            int sup = (lane == 0) ? a0 : (lane == 1) ? a1 : (lane == 2) ? a2 : a3;
            g_sup4[q * NK + kb + lane] = sup;   // written exactly once per replay
        }
    } else if (role < 512) {
        // ---- edge build ----
        int rr = role - 256;
        int jq = rr & 3;            // j quarter
        int ig = rr >> 2;           // i range [ig*64, ig*64+64)
        if (t == 0) s_cnt = 0;
        for (int i = t; i < 1024; i += 256) sj[i] = ep2[jq * 1024 + i];
        for (int i = t; i < 64; i += 256) si[i] = ep2[ig * 64 + i];
        __syncthreads();

        int il  = t >> 2;           // local i (4 threads per i)
        int sub = t & 3;            // j sub-chunk of 256
        int i   = ig * 64 + il;
        float2 pi = si[il];
        int j0 = jq * 1024 + sub * 256;
        int js = sub * 256;
        #pragma unroll 4
        for (int jj = 0; jj < 256; ++jj) {
            float2 e = sj[js + jj];
            float dx = pi.x - e.x;
            float dy = pi.y - e.y;
            int j = j0 + jj;
            if (j > i && dx*dx + dy*dy <= 9.0f) {
                int x = atomicAdd(&s_cnt, 1);
                if (x < EB_CAP) g_edges[rr * EB_CAP + x] = (i << 16) | j;
            }
        }
        __syncthreads();
        if (t == 0) g_bcnt[rr] = s_cnt < EB_CAP ? s_cnt : EB_CAP;
    } else {
        // ---- line-score normalization ----
        float v = -1e30f;
        for (int k = t; k < NLINES; k += 256) v = fmaxf(v, line_sc[k]);
        red[t] = v;
        __syncthreads();
        for (int s = 128; s > 0; s >>= 1) {
            if (t < s) red[t] = fmaxf(red[t], red[t + s]);
            __syncthreads();
        }
        float denom = 1e-8f + red[0];
        for (int k = t; k < NLINES; k += 256) out[OFF_LS + k] = line_sc[k] / denom;
    }
}

// =====================================================================
// k_geom: ONE block x 1024 thr — suppress-merge + kp outputs,
// edge compact, CC, rank, smem fixed-point segment means, small outputs.
// =====================================================================
__global__ void __launch_bounds__(1024) k_geom(const float* __restrict__ lines,
                                               const float* __restrict__ kp,
                                               const float* __restrict__ ksc,
                                               float* __restrict__ out) {
    extern __shared__ int dsm[];
    int* lab  = dsm;             // 4096
    int* rnk  = dsm + 4096;      // 4096
    int* imap = dsm + 8192;      // 4096
    int* ax   = dsm + 12288;     // 4096
    int* ay   = dsm + 16384;     // 4096
    int* as_  = dsm + 20480;     // 4096
    int* cn   = dsm + 24576;     // 4096
    int* sE   = dsm + 28672;     // SE_CAP
    int* scn  = dsm + 29696;     // 1024
    int* soff = dsm + 30720;     // 257
    int* misc = dsm + 30978;     // 2

    int t = threadIdx.x;
    if (t == 0) g_sample_done = 0;      // stream-ordered reset for k_main

    // ---- merge suppression quarters; kp point/score outputs ----
    for (int k = t; k < NK; k += 1024) {
        int sup = g_sup4[k] | g_sup4[NK + k] | g_sup4[2*NK + k] | g_sup4[3*NK + k];
        g_suppress[k] = sup;
        out[OFF_POINTS + 2*(NEP + k)]     = sup ? 0.f : kp[2*k];
        out[OFF_POINTS + 2*(NEP + k) + 1] = sup ? 0.f : kp[2*k + 1];
        out[OFF_SCORES + NEP + k]         = sup ? 0.f : ksc[k];
    }

    if (t == 0) {
        int acc = 0;
        for (int b = 0; b < 256; ++b) { soff[b] = acc; acc += g_bcnt[b]; }
        soff[256] = acc;
    }
    for (int i = t; i < NEP; i += 1024) {
        lab[i] = i;
        ax[i] = 0; ay[i] = 0; as_[i] = 0; cn[i] = 0; imap[i] = -1;
    }
    __syncthreads();
    int E = soff[256]; if (E > SE_CAP) E = SE_CAP;
    for (int s = t; s < 256 * EB_CAP; s += 1024) {
        int b = s >> 6, e = s & (EB_CAP - 1);
        if (e < g_bcnt[b]) { int d = soff[b] + e; if (d < SE_CAP) sE[d] = g_edges[s]; }
    }
    __syncthreads();

    // ---- CC min-label fixpoint (schedule-invariant result) ----
    for (int it = 0; it < 64; ++it) {
        if (t == 0) misc[1] = 0;
        __syncthreads();
        for (int e = t; e < E; e += 1024) {
            int pr = sE[e];
            int i = pr >> 16, j = pr & 0xffff;
            int a = lab[i], b = lab[j];
            if (a < b)      { int old = atomicMin(&lab[j], a); if (old > a) misc[1] = 1; }
            else if (b < a) { int old = atomicMin(&lab[i], b); if (old > b) misc[1] = 1; }
        }
        __syncthreads();
        for (int i = t; i < NEP; i += 1024) {
            int l = lab[i], l2 = lab[l];
            if (l2 < l) { lab[i] = l2; misc[1] = 1; }
        }
        __syncthreads();
        int ch = misc[1];
        __syncthreads();
        if (!ch) break;
    }

    // ---- dense rank of roots ----
    {
        int base = t * 4;
        int p4[4], pre[4], lsum = 0;
        #pragma unroll
        for (int k = 0; k < 4; ++k) {
            p4[k] = (lab[base + k] == base + k) ? 1 : 0;
            pre[k] = lsum;
            lsum += p4[k];
        }
        scn[t] = lsum;
        __syncthreads();
        for (int off = 1; off < 1024; off <<= 1) {
            int add = 0;
            if (t >= off) add = scn[t - off];
            __syncthreads();
            scn[t] += add;
            __syncthreads();
        }
        int excl = scn[t] - lsum;
        #pragma unroll
        for (int k = 0; k < 4; ++k) rnk[base + k] = excl + pre[k];
    }
    __syncthreads();
    for (int i = t; i < NEP; i += 1024)
        if (lab[i] == i) imap[rnk[i]] = i;
    __syncthreads();

    // ---- fixed-point segment sums ----
    const float2* ep2 = (const float2*)lines;
    for (int i = t; i < NEP; i += 1024) {
        float2 e = ep2[i];
        float sc = out[OFF_LS + (i >> 1)];
        int r = lab[i];
        atomicAdd(&ax[r],  __float2int_rn(e.x * FX_COORD));
        atomicAdd(&ay[r],  __float2int_rn(e.y * FX_COORD));
        atomicAdd(&as_[r], __float2int_rn(sc * FX_SCORE));
        atomicAdd(&cn[r], 1);
    }
    __syncthreads();

    for (int s = t; s < NEP; s += 1024) {
        int r = imap[s];
        float jx = 0.f, jy = 0.f, js = 0.f;
        if (r >= 0) {
            float ic = 1.0f / (float)cn[r];
            jx = (float)ax[r]  * (1.0f / FX_COORD) * ic;
            jy = (float)ay[r]  * (1.0f / FX_COORD) * ic;
            js = (float)as_[r] * (1.0f / FX_SCORE) * ic;
        }
        out[OFF_POINTS + 2*s]     = jx;
        out[OFF_POINTS + 2*s + 1] = jy;
        out[OFF_SCORES + s]       = js;
    }
    for (int e = t; e < NEP; e += 1024) {
        int r = lab[e];
        float ic = 1.0f / (float)cn[r];
        out[OFF_NEWLINES + 2*e]     = (float)ax[r] * (1.0f / FX_COORD) * ic;
        out[OFF_NEWLINES + 2*e + 1] = (float)ay[r] * (1.0f / FX_COORD) * ic;
        out[OFF_JIDX + e]           = (float)rnk[r];
    }
}

// =====================================================================
// k_main: 896 blocks x 256 thr, 64KB dyn smem  (R6-proven)
//   [0,256)   : channel-plane staged sampling (unnormalized) -> done++
//   [256,768) : float4 keypoint-descriptor copy (masked)
//   [768,896) : normalize (tail spin; consumers only)
// =====================================================================
__global__ void __launch_bounds__(256) k_main(const float* __restrict__ allD,
                                              const float* __restrict__ desc,
                                              float* __restrict__ out) {
    extern __shared__ float spl[];
    int t = threadIdx.x;
    int role = blockIdx.x;

    if (role < 256) {
        const float4* src = (const float4*)(allD + (size_t)role * (HC * WC));
        float4* dst = (float4*)spl;
        #pragma unroll
        for (int i = 0; i < 16; ++i) dst[i * 256 + t] = src[i * 256 + t];
        __syncthreads();

        float* orow = out + OFF_DESCS + (size_t)role * NTOT;
        const float2* pts = (const float2*)(out + OFF_POINTS);
        #pragma unroll
        for (int it = 0; it < 16; ++it) {
            int p = it * 256 + t;
            float2 pt = pts[p];
            float fx = ((pt.x - 3.5f) / 1019.5f) * 127.0f;
            float fy = ((pt.y - 3.5f) / 1019.5f) * 127.0f;
            float x0 = fminf(fmaxf(floorf(fx), 0.f), 127.f);
            float y0 = fminf(fmaxf(floorf(fy), 0.f), 127.f);
            float x1 = fminf(fmaxf(x0 + 1.0f, 0.f), 127.f);
            float y1 = fminf(fmaxf(y0 + 1.0f, 0.f), 127.f);
            float wx = fx - x0;
            float wy = fy - y0;
            int a00 = (int)y0 * WC + (int)x0;
            int a01 = (int)y0 * WC + (int)x1;
            int a10 = (int)y1 * WC + (int)x0;
            int a11 = (int)y1 * WC + (int)x1;
            float v = spl[a00] * (1.f - wx) * (1.f - wy)
                    + spl[a01] * wx * (1.f - wy)
                    + spl[a10] * (1.f - wx) * wy
                    + spl[a11] * wx * wy;
            orow[p] = v;
        }
        __threadfence();
        __syncthreads();
        if (t == 0) atomicAdd(&g_sample_done, 1);
    } else if (role < 768) {
        int idx = (role - 256) * 256 + t;
        int c  = idx >> 9;
        int kq = idx & 511;
        const float4* d4 = (const float4*)desc;
        float4 v = d4[c * 512 + kq];
        int k4 = kq * 4;
        if (g_suppress[k4])     v.x = 0.f;
        if (g_suppress[k4 + 1]) v.y = 0.f;
        if (g_suppress[k4 + 2]) v.z = 0.f;
        if (g_suppress[k4 + 3]) v.w = 0.f;
        float4* o4 = (float4*)(out + OFF_DESCS + c * NTOT + NEP);
        o4[kq] = v;
    } else {
        if (t == 0) {
            while (atomicAdd(&g_sample_done, 0) < 256) __nanosleep(256);
        }
        __syncthreads();
        __threadfence();

        int w = t >> 5, lane = t & 31;
        int p = (role - 768) * 32 + lane;
        float* ob = out + OFF_DESCS + (size_t)w * 32 * NTOT + p;
        float v[32];
        float ssq = 0.f;
        #pragma unroll
        for (int ci = 0; ci < 32; ++ci) {
            float vv = ob[ci * NTOT];
            v[ci] = vv;
            ssq += vv * vv;
        }
        __shared__ float sred[8][32];
        sred[w][lane] = ssq;
        __syncthreads();
        float tot = sred[0][lane] + sred[1][lane] + sred[2][lane] + sred[3][lane]
                  + sred[4][lane] + sred[5][lane] + sred[6][lane] + sred[7][lane];
        float inv = 1.0f / fmaxf(sqrtf(tot), 1e-12f);
        #pragma unroll
        for (int ci = 0; ci < 32; ++ci)
            ob[ci * NTOT] = v[ci] * inv;
    }
}

// ---------------- launch ----------------
extern "C" void kernel_launch(void* const* d_in, const int* in_sizes, int n_in,
                              void* d_out, int out_size) {
    const float* lines     = (const float*)d_in[0];
    const float* line_sc   = (const float*)d_in[1];
    const float* keypoints = (const float*)d_in[2];
    const float* kp_sc     = (const float*)d_in[3];
    const float* desc      = (const float*)d_in[4];
    const float* allD      = (const float*)d_in[5];
    float* out = (float*)d_out;

    static const int GEOM_SMEM  = (30978 + 4) * 4;   // ~124 KB
    static const int PLANE_SMEM = HC * WC * 4;       // 64 KB
    cudaFuncSetAttribute(k_geom, cudaFuncAttributeMaxDynamicSharedMemorySize, GEOM_SMEM);
    cudaFuncSetAttribute(k_main, cudaFuncAttributeMaxDynamicSharedMemorySize, PLANE_SMEM);

    k_pre<<<513, 256>>>(lines, line_sc, keypoints, out);
    k_geom<<<1, 1024, GEOM_SMEM>>>(lines, keypoints, kp_sc, out);
    k_main<<<896, 256, PLANE_SMEM>>>(allD, desc, out);
}

// round 11
// speedup vs baseline: 2.0277x; 1.5198x over previous
#include <cuda_runtime.h>

// ---------------- problem constants ----------------
#define NLINES 2048
#define NEP    4096
#define NK     2048
#define NC     256
#define NTOT   6144
#define HC     128
#define WC     128
#define EB_CAP 512           // per-edge-block cap (4 blocks, expected ~60 each)
#define SE_CAP 1024

// output offsets (float32, reference return-tuple order)
#define OFF_POINTS   0
#define OFF_SCORES   12288
#define OFF_DESCS    18432
#define OFF_NEWLINES 1591296
#define OFF_JIDX     1599488
#define OFF_LS       1603584

// fixed-point scales (commutative integer sums -> deterministic)
#define FX_COORD 65536.0f
#define FX_SCORE 33554432.0f

// ---------------- global scratch ----------------
__device__ int g_suppress[NK];
__device__ int g_edges[4 * EB_CAP];
__device__ int g_bcnt[4];
__device__ int g_sample_done;

// =====================================================================
// k_pre: 13 blocks x 256 thr, ~83KB dyn smem.
// Every block (except ls-norm) redundantly builds a 64x64 cell grid
// (cell=16) over the 4096 endpoints in smem, then answers its queries:
//   [0,8)  : keypoint suppression (256 kp each) + kp point/score outputs
//   [8,12) : edge build (1024 endpoints each) -> per-block global lists
//   12     : line-score normalization
// =====================================================================
__global__ void __launch_bounds__(256) k_pre(const float* __restrict__ lines,
                                             const float* __restrict__ line_sc,
                                             const float* __restrict__ kp,
                                             const float* __restrict__ ksc,
                                             float* __restrict__ out) {
    extern __shared__ int dsm[];
    int*   cst  = dsm;                    // 4096 cell starts
    int*   ccn  = dsm + 4096;             // 4096 cell counts
    float* sx   = (float*)(dsm + 8192);   // 4096 sorted x
    float* sy   = (float*)(dsm + 12288);  // 4096 sorted y
    int*   sidx = dsm + 16384;            // 4096 orig index
    int*   scn  = dsm + 20480;            // 256 scan tmp
    int*   scnt = dsm + 20736;            // 1 edge counter

    int t = threadIdx.x;
    int role = blockIdx.x;
    const float2* ep2 = (const float2*)lines;

    if (role == 12) {
        // ---- line-score normalization ----
        float* red = (float*)scn;
        float v = -1e30f;
        for (int k = t; k < NLINES; k += 256) v = fmaxf(v, line_sc[k]);
        red[t] = v;
        __syncthreads();
        for (int s = 128; s > 0; s >>= 1) {
            if (t < s) red[t] = fmaxf(red[t], red[t + s]);
            __syncthreads();
        }
        float denom = 1e-8f + red[0];
        for (int k = t; k < NLINES; k += 256) out[OFF_LS + k] = line_sc[k] / denom;
        return;
    }

    // ================= redundant grid build =================
    if (t == 0) scnt[0] = 0;
    for (int i = t; i < 4096; i += 256) ccn[i] = 0;
    __syncthreads();
    for (int i = t; i < 4096; i += 256) {
        float2 e = ep2[i];
        int cx = min(63, max(0, (int)(e.x * 0.0625f)));
        int cy = min(63, max(0, (int)(e.y * 0.0625f)));
        atomicAdd(&ccn[(cy << 6) | cx], 1);
    }
    __syncthreads();
    // exclusive scan of 4096 counts (16 per thread + 256-wide scan)
    {
        int base = t * 16;
        int pre[16], lsum = 0;
        #pragma unroll
        for (int k = 0; k < 16; ++k) { pre[k] = lsum; lsum += ccn[base + k]; }
        scn[t] = lsum;
        __syncthreads();
        for (int off = 1; off < 256; off <<= 1) {
            int add = 0;
            if (t >= off) add = scn[t - off];
            __syncthreads();
            scn[t] += add;
            __syncthreads();
        }
        int excl = scn[t] - lsum;
        #pragma unroll
        for (int k = 0; k < 16; ++k) cst[base + k] = excl + pre[k];
    }
    __syncthreads();
    for (int i = t; i < 4096; i += 256) ccn[i] = 0;
    __syncthreads();
    for (int i = t; i < 4096; i += 256) {
        float2 e = ep2[i];
        int cx = min(63, max(0, (int)(e.x * 0.0625f)));
        int cy = min(63, max(0, (int)(e.y * 0.0625f)));
        int c = (cy << 6) | cx;
        int pos = cst[c] + atomicAdd(&ccn[c], 1);
        sx[pos] = e.x; sy[pos] = e.y; sidx[pos] = i;
    }
    __syncthreads();

    // ================= queries =================
    if (role < 8) {
        // ---- keypoint suppression: dist < 4 (strict) ----
        int k = role * 256 + t;
        float kx = kp[2*k], ky = kp[2*k + 1];
        int x0 = max(0,  (int)floorf((kx - 4.f) * 0.0625f));
        int x1 = min(63, (int)floorf((kx + 4.f) * 0.0625f));
        int y0 = max(0,  (int)floorf((ky - 4.f) * 0.0625f));
        int y1 = min(63, (int)floorf((ky + 4.f) * 0.0625f));
        bool sup = false;
        for (int cy = y0; cy <= y1; ++cy)
            for (int cx = x0; cx <= x1; ++cx) {
                int c = (cy << 6) | cx;
                int st = cst[c], en = st + ccn[c];
                for (int j = st; j < en; ++j) {
                    float dx = kx - sx[j];
                    float dy = ky - sy[j];
                    if (dx*dx + dy*dy < 16.f) sup = true;
                }
            }
        g_suppress[k] = sup ? 1 : 0;
        out[OFF_POINTS + 2*(NEP + k)]     = sup ? 0.f : kx;
        out[OFF_POINTS + 2*(NEP + k) + 1] = sup ? 0.f : ky;
        out[OFF_SCORES + NEP + k]         = sup ? 0.f : ksc[k];
    } else {
        // ---- edge build: d2 <= 9, i < j, per-block list ----
        int b = role - 8;
        for (int ii = t; ii < 1024; ii += 256) {
            int i = b * 1024 + ii;
            float2 e = ep2[i];
            int x0 = max(0,  (int)floorf((e.x - 3.f) * 0.0625f));
            int x1 = min(63, (int)floorf((e.x + 3.f) * 0.0625f));
            int y0 = max(0,  (int)floorf((e.y - 3.f) * 0.0625f));
            int y1 = min(63, (int)floorf((e.y + 3.f) * 0.0625f));
            for (int cy = y0; cy <= y1; ++cy)
                for (int cx = x0; cx <= x1; ++cx) {
                    int c = (cy << 6) | cx;
                    int st = cst[c], en = st + ccn[c];
                    for (int j = st; j < en; ++j) {
                        int oj = sidx[j];
                        if (oj <= i) continue;
                        float dx = e.x - sx[j];
                        float dy = e.y - sy[j];
                        if (dx*dx + dy*dy <= 9.f) {
                            int x = atomicAdd(scnt, 1);
                            if (x < EB_CAP) g_edges[b * EB_CAP + x] = (i << 16) | oj;
                        }
                    }
                }
        }
        __syncthreads();
        if (t == 0) g_bcnt[b] = scnt[0] < EB_CAP ? scnt[0] : EB_CAP;
    }
}

// =====================================================================
// k_geom: ONE block x 1024 thr, slim — edge compact, CC, rank,
// smem fixed-point segment means, small outputs. ~123KB dyn smem.
// =====================================================================
__global__ void __launch_bounds__(1024) k_geom(const float* __restrict__ lines,
                                               float* __restrict__ out) {
    extern __shared__ int dsm[];
    int* lab  = dsm;             // 4096
    int* rnk  = dsm + 4096;      // 4096
    int* imap = dsm + 8192;      // 4096
    int* ax   = dsm + 12288;     // 4096
    int* ay   = dsm + 16384;     // 4096
    int* as_  = dsm + 20480;     // 4096
    int* cn   = dsm + 24576;     // 4096
    int* sE   = dsm + 28672;     // SE_CAP
    int* scn  = dsm + 29696;     // 1024
    int* soff = dsm + 30720;     // 5
    int* misc = dsm + 30726;     // 2

    int t = threadIdx.x;
    if (t == 0) {
        g_sample_done = 0;       // stream-ordered reset for k_main
        int acc = 0;
        for (int b = 0; b < 4; ++b) { soff[b] = acc; acc += g_bcnt[b]; }
        soff[4] = acc;
    }
    for (int i = t; i < NEP; i += 1024) {
        lab[i] = i;
        ax[i] = 0; ay[i] = 0; as_[i] = 0; cn[i] = 0; imap[i] = -1;
    }
    __syncthreads();
    int E = soff[4]; if (E > SE_CAP) E = SE_CAP;
    for (int s = t; s < 4 * EB_CAP; s += 1024) {
        int b = s / EB_CAP, e = s % EB_CAP;
        if (e < g_bcnt[b]) { int d = soff[b] + e; if (d < SE_CAP) sE[d] = g_edges[s]; }
    }
    __syncthreads();

    // CC min-label fixpoint (schedule-invariant result)
    for (int it = 0; it < 64; ++it) {
        if (t == 0) misc[1] = 0;
        __syncthreads();
        for (int e = t; e < E; e += 1024) {
            int pr = sE[e];
            int i = pr >> 16, j = pr & 0xffff;
            int a = lab[i], b = lab[j];
            if (a < b)      { int old = atomicMin(&lab[j], a); if (old > a) misc[1] = 1; }
            else if (b < a) { int old = atomicMin(&lab[i], b); if (old > b) misc[1] = 1; }
        }
        __syncthreads();
        for (int i = t; i < NEP; i += 1024) {
            int l = lab[i], l2 = lab[l];
            if (l2 < l) { lab[i] = l2; misc[1] = 1; }
        }
        __syncthreads();
        int ch = misc[1];
        __syncthreads();
        if (!ch) break;
    }

    // dense rank of roots
    {
        int base = t * 4;
        int p4[4], pre[4], lsum = 0;
        #pragma unroll
        for (int k = 0; k < 4; ++k) {
            p4[k] = (lab[base + k] == base + k) ? 1 : 0;
            pre[k] = lsum;
            lsum += p4[k];
        }
        scn[t] = lsum;
        __syncthreads();
        for (int off = 1; off < 1024; off <<= 1) {
            int add = 0;
            if (t >= off) add = scn[t - off];
            __syncthreads();
            scn[t] += add;
            __syncthreads();
        }
        int excl = scn[t] - lsum;
        #pragma unroll
        for (int k = 0; k < 4; ++k) rnk[base + k] = excl + pre[k];
    }
    __syncthreads();
    for (int i = t; i < NEP; i += 1024)
        if (lab[i] == i) imap[rnk[i]] = i;
    __syncthreads();

    // fixed-point segment sums (smem atomics, commutative)
    const float2* ep2 = (const float2*)lines;
    for (int i = t; i < NEP; i += 1024) {
        float2 e = ep2[i];
        float sc = out[OFF_LS + (i >> 1)];
        int r = lab[i];
        atomicAdd(&ax[r],  __float2int_rn(e.x * FX_COORD));
        atomicAdd(&ay[r],  __float2int_rn(e.y * FX_COORD));
        atomicAdd(&as_[r], __float2int_rn(sc * FX_SCORE));
        atomicAdd(&cn[r], 1);
    }
    __syncthreads();

    for (int s = t; s < NEP; s += 1024) {
        int r = imap[s];
        float jx = 0.f, jy = 0.f, js = 0.f;
        if (r >= 0) {
            float ic = 1.0f / (float)cn[r];
            jx = (float)ax[r]  * (1.0f / FX_COORD) * ic;
            jy = (float)ay[r]  * (1.0f / FX_COORD) * ic;
            js = (float)as_[r] * (1.0f / FX_SCORE) * ic;
        }
        out[OFF_POINTS + 2*s]     = jx;
        out[OFF_POINTS + 2*s + 1] = jy;
        out[OFF_SCORES + s]       = js;
    }
    for (int e = t; e < NEP; e += 1024) {
        int r = lab[e];
        float ic = 1.0f / (float)cn[r];
        out[OFF_NEWLINES + 2*e]     = (float)ax[r] * (1.0f / FX_COORD) * ic;
        out[OFF_NEWLINES + 2*e + 1] = (float)ay[r] * (1.0f / FX_COORD) * ic;
        out[OFF_JIDX + e]           = (float)rnk[r];
    }
}

// =====================================================================
// k_main: 896 blocks x 256 thr, 64KB dyn smem  (R6-proven, 19.2us)
//   [0,256)   : channel-plane staged sampling (unnormalized) -> done++
//   [256,768) : float4 keypoint-descriptor copy (masked)
//   [768,896) : normalize (tail spin; consumers only)
// =====================================================================
__global__ void __launch_bounds__(256) k_main(const float* __restrict__ allD,
                                              const float* __restrict__ desc,
                                              float* __restrict__ out) {
    extern __shared__ float spl[];
    int t = threadIdx.x;
    int role = blockIdx.x;

    if (role < 256) {
        const float4* src = (const float4*)(allD + (size_t)role * (HC * WC));
        float4* dst = (float4*)spl;
        #pragma unroll
        for (int i = 0; i < 16; ++i) dst[i * 256 + t] = src[i * 256 + t];
        __syncthreads();

        float* orow = out + OFF_DESCS + (size_t)role * NTOT;
        const float2* pts = (const float2*)(out + OFF_POINTS);
        #pragma unroll
        for (int it = 0; it < 16; ++it) {
            int p = it * 256 + t;
            float2 pt = pts[p];
            float fx = ((pt.x - 3.5f) / 1019.5f) * 127.0f;
            float fy = ((pt.y - 3.5f) / 1019.5f) * 127.0f;
            float x0 = fminf(fmaxf(floorf(fx), 0.f), 127.f);
            float y0 = fminf(fmaxf(floorf(fy), 0.f), 127.f);
            float x1 = fminf(fmaxf(x0 + 1.0f, 0.f), 127.f);
            float y1 = fminf(fmaxf(y0 + 1.0f, 0.f), 127.f);
            float wx = fx - x0;
            float wy = fy - y0;
            int a00 = (int)y0 * WC + (int)x0;
            int a01 = (int)y0 * WC + (int)x1;
            int a10 = (int)y1 * WC + (int)x0;
            int a11 = (int)y1 * WC + (int)x1;
            float v = spl[a00] * (1.f - wx) * (1.f - wy)
                    + spl[a01] * wx * (1.f - wy)
                    + spl[a10] * (1.f - wx) * wy
                    + spl[a11] * wx * wy;
            orow[p] = v;
        }
        __threadfence();
        __syncthreads();
        if (t == 0) atomicAdd(&g_sample_done, 1);
    } else if (role < 768) {
        int idx = (role - 256) * 256 + t;
        int c  = idx >> 9;
        int kq = idx & 511;
        const float4* d4 = (const float4*)desc;
        float4 v = d4[c * 512 + kq];
        int k4 = kq * 4;
        if (g_suppress[k4])     v.x = 0.f;
        if (g_suppress[k4 + 1]) v.y = 0.f;
        if (g_suppress[k4 + 2]) v.z = 0.f;
        if (g_suppress[k4 + 3]) v.w = 0.f;
        float4* o4 = (float4*)(out + OFF_DESCS + c * NTOT + NEP);
        o4[kq] = v;
    } else {
        if (t == 0) {
            while (atomicAdd(&g_sample_done, 0) < 256) __nanosleep(256);
        }
        __syncthreads();
        __threadfence();

        int w = t >> 5, lane = t & 31;
        int p = (role - 768) * 32 + lane;
        float* ob = out + OFF_DESCS + (size_t)w * 32 * NTOT + p;
        float v[32];
        float ssq = 0.f;
        #pragma unroll
        for (int ci = 0; ci < 32; ++ci) {
            float vv = ob[ci * NTOT];
            v[ci] = vv;
            ssq += vv * vv;
        }
        __shared__ float sred[8][32];
        sred[w][lane] = ssq;
        __syncthreads();
        float tot = sred[0][lane] + sred[1][lane] + sred[2][lane] + sred[3][lane]
                  + sred[4][lane] + sred[5][lane] + sred[6][lane] + sred[7][lane];
        float inv = 1.0f / fmaxf(sqrtf(tot), 1e-12f);
        #pragma unroll
        for (int ci = 0; ci < 32; ++ci)
            ob[ci * NTOT] = v[ci] * inv;
    }
}

// ---------------- launch ----------------
extern "C" void kernel_launch(void* const* d_in, const int* in_sizes, int n_in,
                              void* d_out, int out_size) {
    const float* lines     = (const float*)d_in[0];
    const float* line_sc   = (const float*)d_in[1];
    const float* keypoints = (const float*)d_in[2];
    const float* kp_sc     = (const float*)d_in[3];
    const float* desc      = (const float*)d_in[4];
    const float* allD      = (const float*)d_in[5];
    float* out = (float*)d_out;

    static const int PRE_SMEM   = (20736 + 8) * 4;   // ~83 KB
    static const int GEOM_SMEM  = (30726 + 4) * 4;   // ~123 KB
    static const int PLANE_SMEM = HC * WC * 4;       // 64 KB
    cudaFuncSetAttribute(k_pre,  cudaFuncAttributeMaxDynamicSharedMemorySize, PRE_SMEM);
    cudaFuncSetAttribute(k_geom, cudaFuncAttributeMaxDynamicSharedMemorySize, GEOM_SMEM);
    cudaFuncSetAttribute(k_main, cudaFuncAttributeMaxDynamicSharedMemorySize, PLANE_SMEM);

    k_pre<<<13, 256, PRE_SMEM>>>(lines, line_sc, keypoints, kp_sc, out);
    k_geom<<<1, 1024, GEOM_SMEM>>>(lines, out);
    k_main<<<896, 256, PLANE_SMEM>>>(allD, desc, out);
}

// round 12
// speedup vs baseline: 2.0854x; 1.0285x over previous
#include <cuda_runtime.h>

// ---------------- problem constants ----------------
#define NLINES 2048
#define NEP    4096
#define NK     2048
#define NC     256
#define NTOT   6144
#define HC     128
#define WC     128
#define EB_CAP 512
#define SE_CAP 1024

// output offsets (float32, reference return-tuple order)
#define OFF_POINTS   0
#define OFF_SCORES   12288
#define OFF_DESCS    18432
#define OFF_NEWLINES 1591296
#define OFF_JIDX     1599488
#define OFF_LS       1603584

// fixed-point scales (commutative integer sums -> deterministic)
#define FX_COORD 65536.0f
#define FX_SCORE 33554432.0f

// ---------------- global scratch ----------------
__device__ int g_suppress[NK];
__device__ int g_edges[4 * EB_CAP];
__device__ int g_bcnt[4];
__device__ int g_pre_done;       // reset by k_main (stream-ordered for next replay)
__device__ int g_sample_done;    // reset by k_geo

// =====================================================================
// k_geo: 10 blocks x 512 thr, ~121KB dyn smem.
//   [0,4)  : keypoint suppression (512 kp each) + kp outputs   (grid build)
//   [4,8)  : edge build (1024 eps each) -> global lists        (grid build)
//   8      : line-score normalization            -> g_pre_done++
//   9      : geom: spins g_pre_done==5 (consumer-only; all 10 blocks
//            resident in wave 1, producers never wait) then CC/rank/means.
// =====================================================================
__global__ void __launch_bounds__(512) k_geo(const float* __restrict__ lines,
                                             const float* __restrict__ line_sc,
                                             const float* __restrict__ kp,
                                             const float* __restrict__ ksc,
                                             float* __restrict__ out) {
    extern __shared__ int dsm[];
    int t = threadIdx.x;
    int role = blockIdx.x;
    const float2* ep2 = (const float2*)lines;

    if (role == 8) {
        // ---- line-score normalization ----
        if (t == 0) g_sample_done = 0;        // reset for k_main (stream-ordered)
        float* red = (float*)dsm;
        float v = -1e30f;
        for (int k = t; k < NLINES; k += 512) v = fmaxf(v, line_sc[k]);
        red[t] = v;
        __syncthreads();
        for (int s = 256; s > 0; s >>= 1) {
            if (t < s) red[t] = fmaxf(red[t], red[t + s]);
            __syncthreads();
        }
        float denom = 1e-8f + red[0];
        for (int k = t; k < NLINES; k += 512) out[OFF_LS + k] = line_sc[k] / denom;
        __threadfence();
        __syncthreads();
        if (t == 0) atomicAdd(&g_pre_done, 1);
        return;
    }

    if (role == 9) {
        // ================= geom (pure consumer) =================
        int* lab  = dsm;             // 4096
        int* rnk  = dsm + 4096;      // 4096
        int* imap = dsm + 8192;      // 4096
        int* ax   = dsm + 12288;     // 4096
        int* ay   = dsm + 16384;     // 4096
        int* as_  = dsm + 20480;     // 4096
        int* cn   = dsm + 24576;     // 4096
        int* sE   = dsm + 28672;     // SE_CAP
        int* scn  = dsm + 29696;     // 512
        int* soff = dsm + 30208;     // 5
        int* misc = dsm + 30214;     // 2

        for (int i = t; i < NEP; i += 512) {
            lab[i] = i;
            ax[i] = 0; ay[i] = 0; as_[i] = 0; cn[i] = 0; imap[i] = -1;
        }
        if (t == 0) {
            while (atomicAdd(&g_pre_done, 0) < 5) __nanosleep(128);
        }
        __syncthreads();
        __threadfence();

        if (t == 0) {
            int acc = 0;
            for (int b = 0; b < 4; ++b) { soff[b] = acc; acc += g_bcnt[b]; }
            soff[4] = acc;
        }
        __syncthreads();
        int E = soff[4]; if (E > SE_CAP) E = SE_CAP;
        for (int s = t; s < 4 * EB_CAP; s += 512) {
            int b = s / EB_CAP, e = s % EB_CAP;
            if (e < g_bcnt[b]) { int d = soff[b] + e; if (d < SE_CAP) sE[d] = g_edges[s]; }
        }
        __syncthreads();

        // CC min-label fixpoint (schedule-invariant result)
        for (int it = 0; it < 64; ++it) {
            if (t == 0) misc[1] = 0;
            __syncthreads();
            for (int e = t; e < E; e += 512) {
                int pr = sE[e];
                int i = pr >> 16, j = pr & 0xffff;
                int a = lab[i], b = lab[j];
                if (a < b)      { int old = atomicMin(&lab[j], a); if (old > a) misc[1] = 1; }
                else if (b < a) { int old = atomicMin(&lab[i], b); if (old > b) misc[1] = 1; }
            }
            __syncthreads();
            for (int i = t; i < NEP; i += 512) {
                int l = lab[i], l2 = lab[l];
                if (l2 < l) { lab[i] = l2; misc[1] = 1; }
            }
            __syncthreads();
            int ch = misc[1];
            __syncthreads();
            if (!ch) break;
        }

        // dense rank of roots (8 flags/thread, 512-scan)
        {
            int base = t * 8;
            int p8[8], pre[8], lsum = 0;
            #pragma unroll
            for (int k = 0; k < 8; ++k) {
                p8[k] = (lab[base + k] == base + k) ? 1 : 0;
                pre[k] = lsum;
                lsum += p8[k];
            }
            scn[t] = lsum;
            __syncthreads();
            for (int off = 1; off < 512; off <<= 1) {
                int add = 0;
                if (t >= off) add = scn[t - off];
                __syncthreads();
                scn[t] += add;
                __syncthreads();
            }
            int excl = scn[t] - lsum;
            #pragma unroll
            for (int k = 0; k < 8; ++k) rnk[base + k] = excl + pre[k];
        }
        __syncthreads();
        for (int i = t; i < NEP; i += 512)
            if (lab[i] == i) imap[rnk[i]] = i;
        __syncthreads();

        // fixed-point segment sums (smem atomics, commutative)
        for (int i = t; i < NEP; i += 512) {
            float2 e = ep2[i];
            float sc = out[OFF_LS + (i >> 1)];
            int r = lab[i];
            atomicAdd(&ax[r],  __float2int_rn(e.x * FX_COORD));
            atomicAdd(&ay[r],  __float2int_rn(e.y * FX_COORD));
            atomicAdd(&as_[r], __float2int_rn(sc * FX_SCORE));
            atomicAdd(&cn[r], 1);
        }
        __syncthreads();

        for (int s = t; s < NEP; s += 512) {
            int r = imap[s];
            float jx = 0.f, jy = 0.f, js = 0.f;
            if (r >= 0) {
                float ic = 1.0f / (float)cn[r];
                jx = (float)ax[r]  * (1.0f / FX_COORD) * ic;
                jy = (float)ay[r]  * (1.0f / FX_COORD) * ic;
                js = (float)as_[r] * (1.0f / FX_SCORE) * ic;
            }
            out[OFF_POINTS + 2*s]     = jx;
            out[OFF_POINTS + 2*s + 1] = jy;
            out[OFF_SCORES + s]       = js;
        }
        for (int e = t; e < NEP; e += 512) {
            int r = lab[e];
            float ic = 1.0f / (float)cn[r];
            out[OFF_NEWLINES + 2*e]     = (float)ax[r] * (1.0f / FX_COORD) * ic;
            out[OFF_NEWLINES + 2*e + 1] = (float)ay[r] * (1.0f / FX_COORD) * ic;
            out[OFF_JIDX + e]           = (float)rnk[r];
        }
        return;
    }

    // ================= query blocks: redundant grid build =================
    int*   cst  = dsm;                    // 4096
    int*   ccn  = dsm + 4096;             // 4096
    float* sx   = (float*)(dsm + 8192);   // 4096
    float* sy   = (float*)(dsm + 12288);  // 4096
    int*   sidx = dsm + 16384;            // 4096
    int*   scn  = dsm + 20480;            // 512
    int*   scnt = dsm + 20992;            // 1

    if (t == 0) scnt[0] = 0;
    for (int i = t; i < 4096; i += 512) ccn[i] = 0;
    __syncthreads();
    for (int i = t; i < 4096; i += 512) {
        float2 e = ep2[i];
        int cx = min(63, max(0, (int)(e.x * 0.0625f)));
        int cy = min(63, max(0, (int)(e.y * 0.0625f)));
        atomicAdd(&ccn[(cy << 6) | cx], 1);
    }
    __syncthreads();
    {
        int base = t * 8;
        int pre[8], lsum = 0;
        #pragma unroll
        for (int k = 0; k < 8; ++k) { pre[k] = lsum; lsum += ccn[base + k]; }
        scn[t] = lsum;
        __syncthreads();
        for (int off = 1; off < 512; off <<= 1) {
            int add = 0;
            if (t >= off) add = scn[t - off];
            __syncthreads();
            scn[t] += add;
            __syncthreads();
        }
        int excl = scn[t] - lsum;
        #pragma unroll
        for (int k = 0; k < 8; ++k) cst[base + k] = excl + pre[k];
    }
    __syncthreads();
    for (int i = t; i < 4096; i += 512) ccn[i] = 0;
    __syncthreads();
    for (int i = t; i < 4096; i += 512) {
        float2 e = ep2[i];
        int cx = min(63, max(0, (int)(e.x * 0.0625f)));
        int cy = min(63, max(0, (int)(e.y * 0.0625f)));
        int c = (cy << 6) | cx;
        int pos = cst[c] + atomicAdd(&ccn[c], 1);
        sx[pos] = e.x; sy[pos] = e.y; sidx[pos] = i;
    }
    __syncthreads();

    if (role < 4) {
        // ---- keypoint suppression: dist < 4 ----
        int k = role * 512 + t;
        float kx = kp[2*k], ky = kp[2*k + 1];
        int x0 = max(0,  (int)floorf((kx - 4.f) * 0.0625f));
        int x1 = min(63, (int)floorf((kx + 4.f) * 0.0625f));
        int y0 = max(0,  (int)floorf((ky - 4.f) * 0.0625f));
        int y1 = min(63, (int)floorf((ky + 4.f) * 0.0625f));
        bool sup = false;
        for (int cy = y0; cy <= y1; ++cy)
            for (int cx = x0; cx <= x1; ++cx) {
                int c = (cy << 6) | cx;
                int st = cst[c], en = st + ccn[c];
                for (int j = st; j < en; ++j) {
                    float dx = kx - sx[j];
                    float dy = ky - sy[j];
                    if (dx*dx + dy*dy < 16.f) sup = true;
                }
            }
        g_suppress[k] = sup ? 1 : 0;
        out[OFF_POINTS + 2*(NEP + k)]     = sup ? 0.f : kx;
        out[OFF_POINTS + 2*(NEP + k) + 1] = sup ? 0.f : ky;
        out[OFF_SCORES + NEP + k]         = sup ? 0.f : ksc[k];
    } else {
        // ---- edge build: d2 <= 9, i < j ----
        int b = role - 4;
        for (int ii = t; ii < 1024; ii += 512) {
            int i = b * 1024 + ii;
            float2 e = ep2[i];
            int x0 = max(0,  (int)floorf((e.x - 3.f) * 0.0625f));
            int x1 = min(63, (int)floorf((e.x + 3.f) * 0.0625f));
            int y0 = max(0,  (int)floorf((e.y - 3.f) * 0.0625f));
            int y1 = min(63, (int)floorf((e.y + 3.f) * 0.0625f));
            for (int cy = y0; cy <= y1; ++cy)
                for (int cx = x0; cx <= x1; ++cx) {
                    int c = (cy << 6) | cx;
                    int st = cst[c], en = st + ccn[c];
                    for (int j = st; j < en; ++j) {
                        int oj = sidx[j];
                        if (oj <= i) continue;
                        float dx = e.x - sx[j];
                        float dy = e.y - sy[j];
                        if (dx*dx + dy*dy <= 9.f) {
                            int x = atomicAdd(scnt, 1);
                            if (x < EB_CAP) g_edges[b * EB_CAP + x] = (i << 16) | oj;
                        }
                    }
                }
        }
        __syncthreads();
        if (t == 0) g_bcnt[b] = scnt[0] < EB_CAP ? scnt[0] : EB_CAP;
        __threadfence();
        __syncthreads();
        if (t == 0) atomicAdd(&g_pre_done, 1);
    }
}

// =====================================================================
// k_main: 896 blocks x 512 thr, ~33KB dyn smem (half-plane staging)
//   [0,512)   : samplers; block = (ch, half). Stage 65 rows; own points
//               by y0 (A: y0<=63, B: y0>=64) -> single writer. done++
//   [512,768) : float4 keypoint-descriptor copy (masked)
//   [768,896) : normalize (tail spin until done==512; consumers only)
// =====================================================================
__global__ void __launch_bounds__(512) k_main(const float* __restrict__ allD,
                                              const float* __restrict__ desc,
                                              float* __restrict__ out) {
    extern __shared__ float spl[];      // 65 * 128 floats
    int t = threadIdx.x;
    int role = blockIdx.x;

    if (role == 0 && t == 0) g_pre_done = 0;   // reset for next replay's k_geo

    if (role < 512) {
        int ch   = role >> 1;
        int half = role & 1;
        int rowbase = half ? 63 : 0;            // rows [rowbase, rowbase+65)
        const float4* src = (const float4*)(allD + (size_t)ch * (HC * WC) + rowbase * WC);
        float4* dst = (float4*)spl;
        #pragma unroll
        for (int i = t; i < 65 * WC / 4; i += 512) dst[i] = src[i];
        __syncthreads();

        float* orow = out + OFF_DESCS + (size_t)ch * NTOT;
        const float2* pts = (const float2*)(out + OFF_POINTS);
        #pragma unroll
        for (int it = 0; it < 8; ++it) {
            int p = it * 512 + t;
            float2 pt = pts[p];
            float fx = ((pt.x - 3.5f) / 1019.5f) * 127.0f;
            float fy = ((pt.y - 3.5f) / 1019.5f) * 127.0f;
            float x0 = fminf(fmaxf(floorf(fx), 0.f), 127.f);
            float y0 = fminf(fmaxf(floorf(fy), 0.f), 127.f);
            int yi0 = (int)y0;
            bool own = half ? (yi0 >= 64) : (yi0 <= 63);
            if (own) {
                float x1 = fminf(x0 + 1.0f, 127.f);
                float y1 = fminf(y0 + 1.0f, 127.f);
                float wx = fx - x0;
                float wy = fy - y0;
                int xi0 = (int)x0, xi1 = (int)x1, yi1 = (int)y1;
                int r0 = (yi0 - rowbase) * WC;
                int r1 = (yi1 - rowbase) * WC;
                float v = spl[r0 + xi0] * (1.f - wx) * (1.f - wy)
                        + spl[r0 + xi1] * wx * (1.f - wy)
                        + spl[r1 + xi0] * (1.f - wx) * wy
                        + spl[r1 + xi1] * wx * wy;
                orow[p] = v;
            }
        }
        __threadfence();
        __syncthreads();
        if (t == 0) atomicAdd(&g_sample_done, 1);
    } else if (role < 768) {
        int idx = (role - 512) * 512 + t;       // 131072 float4s
        int c  = idx >> 9;
        int kq = idx & 511;
        const float4* d4 = (const float4*)desc;
        float4 v = d4[c * 512 + kq];
        int k4 = kq * 4;
        if (g_suppress[k4])     v.x = 0.f;
        if (g_suppress[k4 + 1]) v.y = 0.f;
        if (g_suppress[k4 + 2]) v.z = 0.f;
        if (g_suppress[k4 + 3]) v.w = 0.f;
        float4* o4 = (float4*)(out + OFF_DESCS + c * NTOT + NEP);
        o4[kq] = v;
    } else {
        if (t == 0) {
            while (atomicAdd(&g_sample_done, 0) < 512) __nanosleep(256);
        }
        __syncthreads();
        __threadfence();

        int w = t >> 5, lane = t & 31;          // 16 warps x 16 channels
        int p = (role - 768) * 32 + lane;
        float* ob = out + OFF_DESCS + (size_t)w * 16 * NTOT + p;
        float v[16];
        float ssq = 0.f;
        #pragma unroll
        for (int ci = 0; ci < 16; ++ci) {
            float vv = ob[ci * NTOT];
            v[ci] = vv;
            ssq += vv * vv;
        }
        float* sred = spl;                      // [16][32]
        sred[w * 32 + lane] = ssq;
        __syncthreads();
        float tot = 0.f;
        #pragma unroll
        for (int i = 0; i < 16; ++i) tot += sred[i * 32 + lane];
        float inv = 1.0f / fmaxf(sqrtf(tot), 1e-12f);
        #pragma unroll
        for (int ci = 0; ci < 16; ++ci)
            ob[ci * NTOT] = v[ci] * inv;
    }
}

// ---------------- launch ----------------
extern "C" void kernel_launch(void* const* d_in, const int* in_sizes, int n_in,
                              void* d_out, int out_size) {
    const float* lines     = (const float*)d_in[0];
    const float* line_sc   = (const float*)d_in[1];
    const float* keypoints = (const float*)d_in[2];
    const float* kp_sc     = (const float*)d_in[3];
    const float* desc      = (const float*)d_in[4];
    const float* allD      = (const float*)d_in[5];
    float* out = (float*)d_out;

    static const int GEO_SMEM  = (30216 + 8) * 4;   // ~121 KB (max of roles)
    static const int MAIN_SMEM = 65 * WC * 4;       // 33280 B
    cudaFuncSetAttribute(k_geo,  cudaFuncAttributeMaxDynamicSharedMemorySize, GEO_SMEM);
    cudaFuncSetAttribute(k_main, cudaFuncAttributeMaxDynamicSharedMemorySize, MAIN_SMEM);

    k_geo<<<10, 512, GEO_SMEM>>>(lines, line_sc, keypoints, kp_sc, out);
    k_main<<<896, 512, MAIN_SMEM>>>(allD, desc, out);
}

// round 13
// speedup vs baseline: 2.2229x; 1.0659x over previous
#include <cuda_runtime.h>

// ---------------- problem constants ----------------
#define NLINES 2048
#define NEP    4096
#define NK     2048
#define NC     256
#define NTOT   6144
#define HC     128
#define WC     128
#define EB_CAP 512
#define SE_CAP 1024

// output offsets (float32, reference return-tuple order)
#define OFF_POINTS   0
#define OFF_SCORES   12288
#define OFF_DESCS    18432
#define OFF_NEWLINES 1591296
#define OFF_JIDX     1599488
#define OFF_LS       1603584

// fixed-point scales (commutative integer sums -> deterministic)
#define FX_COORD 65536.0f
#define FX_SCORE 33554432.0f

// ---------------- global scratch ----------------
__device__ int g_suppress[NK];
__device__ int g_edges[4 * EB_CAP];
__device__ int g_bcnt[4];
__device__ int g_pre_done;       // reset by k_main role 0 (stream-ordered)
__device__ int g_sample_done;    // reset by k_geo ls role

// =====================================================================
// k_geo: 8 blocks x 1024 thr, ~123KB dyn smem.
//   [0,2) : keypoint suppression (1024 kp each) + kp outputs  (grid build)
//   [2,6) : edge build (1024 eps each) -> global lists        (grid build)
//   6     : line-score normalization             -> g_pre_done++
//   7     : geom: spins g_pre_done==5 (pure consumer; all 8 blocks
//           resident in wave 1) then CC/rank/segment means/outputs.
// =====================================================================
__global__ void __launch_bounds__(1024) k_geo(const float* __restrict__ lines,
                                              const float* __restrict__ line_sc,
                                              const float* __restrict__ kp,
                                              const float* __restrict__ ksc,
                                              float* __restrict__ out) {
    extern __shared__ int dsm[];
    int t = threadIdx.x;
    int role = blockIdx.x;
    const float2* ep2 = (const float2*)lines;

    if (role == 6) {
        // ---- line-score normalization ----
        if (t == 0) g_sample_done = 0;        // reset for k_main
        float* red = (float*)dsm;
        float v = -1e30f;
        for (int k = t; k < NLINES; k += 1024) v = fmaxf(v, line_sc[k]);
        red[t] = v;
        __syncthreads();
        for (int s = 512; s > 0; s >>= 1) {
            if (t < s) red[t] = fmaxf(red[t], red[t + s]);
            __syncthreads();
        }
        float denom = 1e-8f + red[0];
        for (int k = t; k < NLINES; k += 1024) out[OFF_LS + k] = line_sc[k] / denom;
        __threadfence();
        __syncthreads();
        if (t == 0) atomicAdd(&g_pre_done, 1);
        return;
    }

    if (role == 7) {
        // ================= geom (pure consumer) =================
        int* lab  = dsm;             // 4096
        int* rnk  = dsm + 4096;      // 4096
        int* imap = dsm + 8192;      // 4096
        int* ax   = dsm + 12288;     // 4096
        int* ay   = dsm + 16384;     // 4096
        int* as_  = dsm + 20480;     // 4096
        int* cn   = dsm + 24576;     // 4096
        int* sE   = dsm + 28672;     // SE_CAP
        int* scn  = dsm + 29696;     // 1024
        int* soff = dsm + 30720;     // 5
        int* misc = dsm + 30726;     // 2

        for (int i = t; i < NEP; i += 1024) {
            lab[i] = i;
            ax[i] = 0; ay[i] = 0; as_[i] = 0; cn[i] = 0; imap[i] = -1;
        }
        if (t == 0) {
            while (atomicAdd(&g_pre_done, 0) < 5) __nanosleep(128);
        }
        __syncthreads();
        __threadfence();

        if (t == 0) {
            int acc = 0;
            for (int b = 0; b < 4; ++b) { soff[b] = acc; acc += g_bcnt[b]; }
            soff[4] = acc;
        }
        __syncthreads();
        int E = soff[4]; if (E > SE_CAP) E = SE_CAP;
        for (int s = t; s < 4 * EB_CAP; s += 1024) {
            int b = s / EB_CAP, e = s % EB_CAP;
            if (e < g_bcnt[b]) { int d = soff[b] + e; if (d < SE_CAP) sE[d] = g_edges[s]; }
        }
        __syncthreads();

        // CC min-label fixpoint (schedule-invariant result)
        for (int it = 0; it < 64; ++it) {
            if (t == 0) misc[1] = 0;
            __syncthreads();
            for (int e = t; e < E; e += 1024) {
                int pr = sE[e];
                int i = pr >> 16, j = pr & 0xffff;
                int a = lab[i], b = lab[j];
                if (a < b)      { int old = atomicMin(&lab[j], a); if (old > a) misc[1] = 1; }
                else if (b < a) { int old = atomicMin(&lab[i], b); if (old > b) misc[1] = 1; }
            }
            __syncthreads();
            for (int i = t; i < NEP; i += 1024) {
                int l = lab[i], l2 = lab[l];
                if (l2 < l) { lab[i] = l2; misc[1] = 1; }
            }
            __syncthreads();
            int ch = misc[1];
            __syncthreads();
            if (!ch) break;
        }

        // dense rank of roots (4 flags/thread, 1024-scan)
        {
            int base = t * 4;
            int p4[4], pre[4], lsum = 0;
            #pragma unroll
            for (int k = 0; k < 4; ++k) {
                p4[k] = (lab[base + k] == base + k) ? 1 : 0;
                pre[k] = lsum;
                lsum += p4[k];
            }
            scn[t] = lsum;
            __syncthreads();
            for (int off = 1; off < 1024; off <<= 1) {
                int add = 0;
                if (t >= off) add = scn[t - off];
                __syncthreads();
                scn[t] += add;
                __syncthreads();
            }
            int excl = scn[t] - lsum;
            #pragma unroll
            for (int k = 0; k < 4; ++k) rnk[base + k] = excl + pre[k];
        }
        __syncthreads();
        for (int i = t; i < NEP; i += 1024)
            if (lab[i] == i) imap[rnk[i]] = i;
        __syncthreads();

        // fixed-point segment sums (smem atomics, commutative)
        for (int i = t; i < NEP; i += 1024) {
            float2 e = ep2[i];
            float sc = out[OFF_LS + (i >> 1)];
            int r = lab[i];
            atomicAdd(&ax[r],  __float2int_rn(e.x * FX_COORD));
            atomicAdd(&ay[r],  __float2int_rn(e.y * FX_COORD));
            atomicAdd(&as_[r], __float2int_rn(sc * FX_SCORE));
            atomicAdd(&cn[r], 1);
        }
        __syncthreads();

        for (int s = t; s < NEP; s += 1024) {
            int r = imap[s];
            float jx = 0.f, jy = 0.f, js = 0.f;
            if (r >= 0) {
                float ic = 1.0f / (float)cn[r];
                jx = (float)ax[r]  * (1.0f / FX_COORD) * ic;
                jy = (float)ay[r]  * (1.0f / FX_COORD) * ic;
                js = (float)as_[r] * (1.0f / FX_SCORE) * ic;
            }
            out[OFF_POINTS + 2*s]     = jx;
            out[OFF_POINTS + 2*s + 1] = jy;
            out[OFF_SCORES + s]       = js;
        }
        for (int e = t; e < NEP; e += 1024) {
            int r = lab[e];
            float ic = 1.0f / (float)cn[r];
            out[OFF_NEWLINES + 2*e]     = (float)ax[r] * (1.0f / FX_COORD) * ic;
            out[OFF_NEWLINES + 2*e + 1] = (float)ay[r] * (1.0f / FX_COORD) * ic;
            out[OFF_JIDX + e]           = (float)rnk[r];
        }
        return;
    }

    // ================= query blocks: redundant grid build =================
    int*   cst  = dsm;                    // 4096
    int*   ccn  = dsm + 4096;             // 4096
    float* sx   = (float*)(dsm + 8192);   // 4096
    float* sy   = (float*)(dsm + 12288);  // 4096
    int*   sidx = dsm + 16384;            // 4096
    int*   scn  = dsm + 20480;            // 1024
    int*   scnt = dsm + 21504;            // 1

    if (t == 0) scnt[0] = 0;
    for (int i = t; i < 4096; i += 1024) ccn[i] = 0;
    __syncthreads();
    for (int i = t; i < 4096; i += 1024) {
        float2 e = ep2[i];
        int cx = min(63, max(0, (int)(e.x * 0.0625f)));
        int cy = min(63, max(0, (int)(e.y * 0.0625f)));
        atomicAdd(&ccn[(cy << 6) | cx], 1);
    }
    __syncthreads();
    {
        int base = t * 4;
        int pre[4], lsum = 0;
        #pragma unroll
        for (int k = 0; k < 4; ++k) { pre[k] = lsum; lsum += ccn[base + k]; }
        scn[t] = lsum;
        __syncthreads();
        for (int off = 1; off < 1024; off <<= 1) {
            int add = 0;
            if (t >= off) add = scn[t - off];
            __syncthreads();
            scn[t] += add;
            __syncthreads();
        }
        int excl = scn[t] - lsum;
        #pragma unroll
        for (int k = 0; k < 4; ++k) cst[base + k] = excl + pre[k];
    }
    __syncthreads();
    for (int i = t; i < 4096; i += 1024) ccn[i] = 0;
    __syncthreads();
    for (int i = t; i < 4096; i += 1024) {
        float2 e = ep2[i];
        int cx = min(63, max(0, (int)(e.x * 0.0625f)));
        int cy = min(63, max(0, (int)(e.y * 0.0625f)));
        int c = (cy << 6) | cx;
        int pos = cst[c] + atomicAdd(&ccn[c], 1);
        sx[pos] = e.x; sy[pos] = e.y; sidx[pos] = i;
    }
    __syncthreads();

    if (role < 2) {
        // ---- keypoint suppression: dist < 4 ----
        int k = role * 1024 + t;
        float kx = kp[2*k], ky = kp[2*k + 1];
        int x0 = max(0,  (int)floorf((kx - 4.f) * 0.0625f));
        int x1 = min(63, (int)floorf((kx + 4.f) * 0.0625f));
        int y0 = max(0,  (int)floorf((ky - 4.f) * 0.0625f));
        int y1 = min(63, (int)floorf((ky + 4.f) * 0.0625f));
        bool sup = false;
        for (int cy = y0; cy <= y1; ++cy)
            for (int cx = x0; cx <= x1; ++cx) {
                int c = (cy << 6) | cx;
                int st = cst[c], en = st + ccn[c];
                for (int j = st; j < en; ++j) {
                    float dx = kx - sx[j];
                    float dy = ky - sy[j];
                    if (dx*dx + dy*dy < 16.f) sup = true;
                }
            }
        g_suppress[k] = sup ? 1 : 0;
        out[OFF_POINTS + 2*(NEP + k)]     = sup ? 0.f : kx;
        out[OFF_POINTS + 2*(NEP + k) + 1] = sup ? 0.f : ky;
        out[OFF_SCORES + NEP + k]         = sup ? 0.f : ksc[k];
    } else {
        // ---- edge build: d2 <= 9, i < j ----
        int b = role - 2;
        {
            int i = b * 1024 + t;
            float2 e = ep2[i];
            int x0 = max(0,  (int)floorf((e.x - 3.f) * 0.0625f));
            int x1 = min(63, (int)floorf((e.x + 3.f) * 0.0625f));
            int y0 = max(0,  (int)floorf((e.y - 3.f) * 0.0625f));
            int y1 = min(63, (int)floorf((e.y + 3.f) * 0.0625f));
            for (int cy = y0; cy <= y1; ++cy)
                for (int cx = x0; cx <= x1; ++cx) {
                    int c = (cy << 6) | cx;
                    int st = cst[c], en = st + ccn[c];
                    for (int j = st; j < en; ++j) {
                        int oj = sidx[j];
                        if (oj <= i) continue;
                        float dx = e.x - sx[j];
                        float dy = e.y - sy[j];
                        if (dx*dx + dy*dy <= 9.f) {
                            int x = atomicAdd(scnt, 1);
                            if (x < EB_CAP) g_edges[b * EB_CAP + x] = (i << 16) | oj;
                        }
                    }
                }
        }
        __syncthreads();
        if (t == 0) g_bcnt[b] = scnt[0] < EB_CAP ? scnt[0] : EB_CAP;
        __threadfence();
        __syncthreads();
        if (t == 0) atomicAdd(&g_pre_done, 1);
    }
}

// =====================================================================
// k_main: 640 blocks x 512 thr, ~33KB dyn smem
//   [0,512)   : samplers; block = (ch, half-plane). done++
//   [512,640) : copy-then-normalize: do 1024 float4s of masked kp-desc
//               copy (independent), then tail-spin until done==512,
//               then L2-normalize 32 point columns.
// Producers (samplers) never wait -> no wave convoy.
// =====================================================================
__global__ void __launch_bounds__(512) k_main(const float* __restrict__ allD,
                                              const float* __restrict__ desc,
                                              float* __restrict__ out) {
    extern __shared__ float spl[];      // 65 * 128 floats
    int t = threadIdx.x;
    int role = blockIdx.x;

    if (role == 0 && t == 0) g_pre_done = 0;   // reset for next replay's k_geo

    if (role < 512) {
        int ch   = role >> 1;
        int half = role & 1;
        int rowbase = half ? 63 : 0;            // rows [rowbase, rowbase+65)
        const float4* src = (const float4*)(allD + (size_t)ch * (HC * WC) + rowbase * WC);
        float4* dst = (float4*)spl;
        #pragma unroll
        for (int i = t; i < 65 * WC / 4; i += 512) dst[i] = src[i];
        __syncthreads();

        float* orow = out + OFF_DESCS + (size_t)ch * NTOT;
        const float2* pts = (const float2*)(out + OFF_POINTS);
        #pragma unroll
        for (int it = 0; it < 8; ++it) {
            int p = it * 512 + t;
            float2 pt = pts[p];
            float fx = ((pt.x - 3.5f) / 1019.5f) * 127.0f;
            float fy = ((pt.y - 3.5f) / 1019.5f) * 127.0f;
            float x0 = fminf(fmaxf(floorf(fx), 0.f), 127.f);
            float y0 = fminf(fmaxf(floorf(fy), 0.f), 127.f);
            int yi0 = (int)y0;
            bool own = half ? (yi0 >= 64) : (yi0 <= 63);
            if (own) {
                float x1 = fminf(x0 + 1.0f, 127.f);
                float y1 = fminf(y0 + 1.0f, 127.f);
                float wx = fx - x0;
                float wy = fy - y0;
                int xi0 = (int)x0, xi1 = (int)x1, yi1 = (int)y1;
                int r0 = (yi0 - rowbase) * WC;
                int r1 = (yi1 - rowbase) * WC;
                float v = spl[r0 + xi0] * (1.f - wx) * (1.f - wy)
                        + spl[r0 + xi1] * wx * (1.f - wy)
                        + spl[r1 + xi0] * (1.f - wx) * wy
                        + spl[r1 + xi1] * wx * wy;
                orow[p] = v;
            }
        }
        __threadfence();
        __syncthreads();
        if (t == 0) atomicAdd(&g_sample_done, 1);
    } else {
        // ---- independent copy work first (overlaps sampling) ----
        int cb = role - 512;                    // 0..127
        const float4* d4 = (const float4*)desc;
        #pragma unroll
        for (int it = 0; it < 2; ++it) {
            int idx = cb * 1024 + it * 512 + t; // 131072 float4s total
            int c  = idx >> 9;
            int kq = idx & 511;
            float4 v = d4[c * 512 + kq];
            int k4 = kq * 4;
            if (g_suppress[k4])     v.x = 0.f;
            if (g_suppress[k4 + 1]) v.y = 0.f;
            if (g_suppress[k4 + 2]) v.z = 0.f;
            if (g_suppress[k4 + 3]) v.w = 0.f;
            float4* o4 = (float4*)(out + OFF_DESCS + c * NTOT + NEP);
            o4[kq] = v;
        }

        // ---- tail spin, then normalize ----
        if (t == 0) {
            while (atomicAdd(&g_sample_done, 0) < 512) __nanosleep(256);
        }
        __syncthreads();
        __threadfence();

        int w = t >> 5, lane = t & 31;          // 16 warps x 16 channels
        int p = cb * 32 + lane;
        float* ob = out + OFF_DESCS + (size_t)w * 16 * NTOT + p;
        float v[16];
        float ssq = 0.f;
        #pragma unroll
        for (int ci = 0; ci < 16; ++ci) {
            float vv = ob[ci * NTOT];
            v[ci] = vv;
            ssq += vv * vv;
        }
        float* sred = spl;                      // [16][32]
        sred[w * 32 + lane] = ssq;
        __syncthreads();
        float tot = 0.f;
        #pragma unroll
        for (int i = 0; i < 16; ++i) tot += sred[i * 32 + lane];
        float inv = 1.0f / fmaxf(sqrtf(tot), 1e-12f);
        #pragma unroll
        for (int ci = 0; ci < 16; ++ci)
            ob[ci * NTOT] = v[ci] * inv;
    }
}

// ---------------- launch ----------------
extern "C" void kernel_launch(void* const* d_in, const int* in_sizes, int n_in,
                              void* d_out, int out_size) {
    const float* lines     = (const float*)d_in[0];
    const float* line_sc   = (const float*)d_in[1];
    const float* keypoints = (const float*)d_in[2];
    const float* kp_sc     = (const float*)d_in[3];
    const float* desc      = (const float*)d_in[4];
    const float* allD      = (const float*)d_in[5];
    float* out = (float*)d_out;

    static const int GEO_SMEM  = (30728 + 8) * 4;   // ~123 KB (max of roles)
    static const int MAIN_SMEM = 65 * WC * 4;       // 33280 B
    cudaFuncSetAttribute(k_geo,  cudaFuncAttributeMaxDynamicSharedMemorySize, GEO_SMEM);
    cudaFuncSetAttribute(k_main, cudaFuncAttributeMaxDynamicSharedMemorySize, MAIN_SMEM);

    k_geo<<<8, 1024, GEO_SMEM>>>(lines, line_sc, keypoints, kp_sc, out);
    k_main<<<640, 512, MAIN_SMEM>>>(allD, desc, out);
}